// round 11
// baseline (speedup 1.0000x reference)
#include <cuda_runtime.h>
#include <cuda_fp16.h>
#include <math.h>
#include <stdint.h>

// ---------------------------------------------------------------------------
// Problem constants
// ---------------------------------------------------------------------------
#define R_ROIS 2048
#define CCH    512
#define HWDIM  64
#define DDIM   4096
#define NCLS   21
#define KHALF  2048
#define NORI   58            // valid 7x7-window origins per axis (0..57)

#define OUT_DM 0
#define OUT_DR (R_ROIS * NCLS)
#define OUT_SC (2 * R_ROIS * NCLS)

// ---------------------------------------------------------------------------
// Scratch (device globals)
// ---------------------------------------------------------------------------
__device__ float g_vmax[NORI * NORI * CCH];          // 7x7 max, [y'][x'][c]
__device__ __half g_yh[R_ROIS * KHALF];
__device__ __half g_yl[R_ROIS * KHALF];
__device__ __half g_w6h[DDIM * KHALF];
__device__ __half g_w7h[DDIM * DDIM];
__device__ __half g_h1h[R_ROIS * DDIM];
__device__ __half g_h1l[R_ROIS * DDIM];
__device__ float g_h2[R_ROIS * DDIM];
__device__ float g_hpart[8 * R_ROIS * 48];
__device__ float g_xc[R_ROIS * NCLS];
__device__ float g_xd[R_ROIS * NCLS];
__device__ float g_colmax[NCLS];
__device__ float g_colsum[NCLS];

// ---------------------------------------------------------------------------
// Helpers
// ---------------------------------------------------------------------------
__device__ __forceinline__ uint32_t smem_u32(const void* p) {
    uint32_t a;
    asm("{ .reg .u64 t; cvta.to.shared.u64 t, %1; cvt.u32.u64 %0, t; }" : "=r"(a) : "l"(p));
    return a;
}

__device__ __forceinline__ void split2h(float v, __half& h, __half& l) {
    h = __float2half_rn(v);
    l = __float2half_rn(v - __half2float(h));
}

// swizzled byte offset inside a [rows x 64 fp16] (128 B/row) tile
__device__ __forceinline__ uint32_t swz(int r, int g) {
    return (uint32_t)(r >> 3) * 1024u + (uint32_t)(r & 7) * 128u
         + (uint32_t)((g ^ (r & 7)) << 4);
}

#define CP_ASYNC16(dst, src) \
    asm volatile("cp.async.cg.shared.global [%0], [%1], 16;" :: "r"(dst), "l"(src))
#define CP_COMMIT() asm volatile("cp.async.commit_group;" ::: "memory")
#define CP_WAIT1()  asm volatile("cp.async.wait_group 1;" ::: "memory")

#define LDSM_X4(r0, r1, r2, r3, addr) \
    asm volatile("ldmatrix.sync.aligned.m8n8.x4.shared.b16 {%0,%1,%2,%3}, [%4];" \
                 : "=r"(r0), "=r"(r1), "=r"(r2), "=r"(r3) : "r"(addr))

#define MMA_F16(c, a0, a1, a2, a3, b0, b1) \
    asm volatile("mma.sync.aligned.m16n8k16.row.col.f32.f16.f16.f32 " \
                 "{%0,%1,%2,%3}, {%4,%5,%6,%7}, {%8,%9}, {%0,%1,%2,%3};" \
                 : "+f"((c)[0]), "+f"((c)[1]), "+f"((c)[2]), "+f"((c)[3]) \
                 : "r"(a0), "r"(a1), "r"(a2), "r"(a3), "r"(b0), "r"(b1))

// ---------------------------------------------------------------------------
// Fused SPP pool: 7x7 sliding max, output [y'][x'][c] with coalesced writes.
// ---------------------------------------------------------------------------
#define POOL_SMEM (32 * 7 * 61 * 4)

__global__ __launch_bounds__(256) void pool_kernel(const float* __restrict__ x) {
    extern __shared__ float hm[];
    int yp = blockIdx.x;
    int cg = blockIdx.y;
    int t = threadIdx.x;

    for (int idx = t; idx < 32 * 7 * NORI; idx += 256) {
        int xp = idx % NORI;
        int cy = idx / NORI;             // c*7 + y
        int y = cy % 7, c = cy / 7;
        const float* src = x + ((size_t)(cg * 32 + c) * HWDIM + (yp + y)) * HWDIM + xp;
        float m = src[0];
#pragma unroll
        for (int d = 1; d < 7; d++) m = fmaxf(m, src[d]);
        hm[cy * 61 + xp] = m;
    }
    __syncthreads();

    for (int idx = t; idx < NORI * 32; idx += 256) {
        int c = idx & 31;
        int xp = idx >> 5;
        float m = hm[(c * 7) * 61 + xp];
#pragma unroll
        for (int y = 1; y < 7; y++) m = fmaxf(m, hm[(c * 7 + y) * 61 + xp]);
        g_vmax[((size_t)yp * NORI + xp) * CCH + cg * 32 + c] = m;
    }
}

// ---------------------------------------------------------------------------
// SPP gather: per ROI, y[r, c*4 + q] from g_vmax; write fp16 hi/lo
// ---------------------------------------------------------------------------
__global__ __launch_bounds__(256) void spp_gather_kernel(const int* __restrict__ ssw) {
    __shared__ float ys[KHALF];
    int r = blockIdx.x;
    int y0 = ssw[r * 4 + 0];
    int x0 = ssw[r * 4 + 1];
    int t = threadIdx.x;
#pragma unroll
    for (int q = 0; q < 4; q++) {
        int i = q >> 1, j = q & 1;
        const float* src = g_vmax + ((size_t)(y0 + 7 * i) * NORI + (x0 + 7 * j)) * CCH;
        for (int c0 = 0; c0 < CCH; c0 += 256) {
            int c = c0 + t;
            ys[c * 4 + q] = src[c];
        }
    }
    __syncthreads();
    int k0 = t * 8;
    __half hv[8], lv[8];
#pragma unroll
    for (int u = 0; u < 8; u++) split2h(ys[k0 + u], hv[u], lv[u]);
    *reinterpret_cast<uint4*>(&g_yh[(size_t)r * KHALF + k0]) = *reinterpret_cast<uint4*>(hv);
    *reinterpret_cast<uint4*>(&g_yl[(size_t)r * KHALF + k0]) = *reinterpret_cast<uint4*>(lv);
}

// ---------------------------------------------------------------------------
// Weight fold + fp16 conversion (hi only; B-side single-rounded)
// ---------------------------------------------------------------------------
__global__ __launch_bounds__(256) void wsum_h_kernel(const float* __restrict__ w6) {
    int t = blockIdx.x * blockDim.x + threadIdx.x;
    const int NQ = DDIM * KHALF / 4;
    if (t >= NQ) return;
    int e = t / (KHALF / 4);
    int kq = t - e * (KHALF / 4);
    float4 av = reinterpret_cast<const float4*>(w6 + (size_t)e * DDIM)[kq];
    float4 bv = reinterpret_cast<const float4*>(w6 + (size_t)e * DDIM + KHALF)[kq];
    __half hv[4];
    hv[0] = __float2half_rn(av.x + bv.x);
    hv[1] = __float2half_rn(av.y + bv.y);
    hv[2] = __float2half_rn(av.z + bv.z);
    hv[3] = __float2half_rn(av.w + bv.w);
    *reinterpret_cast<uint2*>(&g_w6h[(size_t)e * KHALF + kq * 4]) = *reinterpret_cast<uint2*>(hv);
}

__global__ __launch_bounds__(256) void w7_h_kernel(const float* __restrict__ w7) {
    int t = blockIdx.x * blockDim.x + threadIdx.x;
    const int NQ = DDIM * DDIM / 4;
    if (t >= NQ) return;
    float4 v = reinterpret_cast<const float4*>(w7)[t];
    __half hv[4];
    hv[0] = __float2half_rn(v.x);
    hv[1] = __float2half_rn(v.y);
    hv[2] = __float2half_rn(v.z);
    hv[3] = __float2half_rn(v.w);
    *reinterpret_cast<uint2*>(&g_w7h[(size_t)t * 4]) = *reinterpret_cast<uint2*>(hv);
}

// ---------------------------------------------------------------------------
// fp16x2 GEMM via mma.sync: C = relu(bias + A·B^T), A = Ah+Al exact pair,
// B = Bh single-rounded. acc = Ah·Bh + Al·Bh.
// CTA tile 64x64, K-chunk 64. 128 threads (4 warps), warp tile 32x32.
// Stage: Ah 8KB + Al 8KB + Bh 8KB = 24KB; 3-stage (72KB) -> 3 CTAs/SM.
// Single __syncthreads per chunk; prefetch distance 2 issued right after sync.
// mode 0: fp32 out; mode 1: fp16 hi/lo out.
// ---------------------------------------------------------------------------
#define STAGE_B 24576
#define GEMM_SMEM (3 * STAGE_B)

__device__ __forceinline__ void load_stage(
    const __half* __restrict__ Ah, const __half* __restrict__ Al,
    const __half* __restrict__ Bh,
    int Kb, int bm0, int bn0, int k0, uint32_t sbase, int tid) {
#pragma unroll
    for (int it = 0; it < 12; it++) {
        int f = tid + it * 128;            // 0..1535 uint4 slots
        const __half* src;
        uint32_t dst;
        if (f < 512) {                     // Ah: 64 rows x 8 groups
            int r = f >> 3, g = f & 7;
            src = Ah + (size_t)(bm0 + r) * Kb + k0 + g * 8;
            dst = sbase + swz(r, g);
        } else if (f < 1024) {             // Al
            int fl = f - 512;
            int r = fl >> 3, g = fl & 7;
            src = Al + (size_t)(bm0 + r) * Kb + k0 + g * 8;
            dst = sbase + 8192u + swz(r, g);
        } else {                           // Bh: 64 rows x 8 groups
            int fl = f - 1024;
            int r = fl >> 3, g = fl & 7;
            src = Bh + (size_t)(bn0 + r) * Kb + k0 + g * 8;
            dst = sbase + 16384u + swz(r, g);
        }
        CP_ASYNC16(dst, src);
    }
}

__global__ __launch_bounds__(128, 3) void gemm_mma(
    const __half* __restrict__ Ah, const __half* __restrict__ Al,
    const __half* __restrict__ Bh,
    const float* __restrict__ bias, int Kb, int mode,
    float* __restrict__ Cf, __half* __restrict__ Ch, __half* __restrict__ Cl) {
    extern __shared__ __align__(128) char smp[];
    uint32_t s0 = smem_u32(smp);

    int tid = threadIdx.x;
    int wid = tid >> 5;
    int lane = tid & 31;
    int wm = wid & 1;          // warp row: 32 M-rows
    int wn = wid >> 1;         // warp col: 32 N-cols
    int bm0 = blockIdx.y * 64;
    int bn0 = blockIdx.x * 64;

    int lr = lane & 7;
    int a_add8 = (lane >> 3) & 1;
    int a_gsel = lane >> 4;
    int b_add8 = lane >> 4;
    int b_gsel = (lane >> 3) & 1;

    uint32_t aoff[2], boff[2];
#pragma unroll
    for (int mf = 0; mf < 2; mf++)
        aoff[mf] = (uint32_t)(wm * 4 + mf * 2 + a_add8) * 1024u + (uint32_t)lr * 128u;
#pragma unroll
    for (int nf2 = 0; nf2 < 2; nf2++)
        boff[nf2] = (uint32_t)(wn * 4 + nf2 * 2 + b_add8) * 1024u + (uint32_t)lr * 128u;

    float acc[2][4][4];
#pragma unroll
    for (int i = 0; i < 2; i++)
#pragma unroll
        for (int j = 0; j < 4; j++)
#pragma unroll
            for (int q = 0; q < 4; q++) acc[i][j][q] = 0.f;

    int nch = Kb >> 6;

    load_stage(Ah, Al, Bh, Kb, bm0, bn0, 0, s0, tid);
    CP_COMMIT();
    load_stage(Ah, Al, Bh, Kb, bm0, bn0, 64, s0 + STAGE_B, tid);
    CP_COMMIT();

    for (int kb = 0; kb < nch; kb++) {
        CP_WAIT1();
        __syncthreads();

        // prefetch chunk kb+2 immediately (its stage = chunk kb-1's, freed by barrier)
        int nk = kb + 2;
        if (nk < nch) {
            load_stage(Ah, Al, Bh, Kb, bm0, bn0, nk * 64,
                       s0 + (uint32_t)(nk % 3) * STAGE_B, tid);
        }
        CP_COMMIT();

        uint32_t abase = s0 + (uint32_t)(kb % 3) * STAGE_B;
        uint32_t albase = abase + 8192u;
        uint32_t bbase = abase + 16384u;

#pragma unroll
        for (int ks = 0; ks < 4; ks++) {
            uint32_t b[2][4];
#pragma unroll
            for (int nf2 = 0; nf2 < 2; nf2++) {
                uint32_t addr = bbase + boff[nf2] + (uint32_t)(((2 * ks + b_gsel) ^ lr) << 4);
                LDSM_X4(b[nf2][0], b[nf2][1], b[nf2][2], b[nf2][3], addr);
            }
            uint32_t a[2][4];
#pragma unroll
            for (int mf = 0; mf < 2; mf++) {
                uint32_t addr = abase + aoff[mf] + (uint32_t)(((2 * ks + a_gsel) ^ lr) << 4);
                LDSM_X4(a[mf][0], a[mf][1], a[mf][2], a[mf][3], addr);
            }
#pragma unroll
            for (int mf = 0; mf < 2; mf++)
#pragma unroll
                for (int nf = 0; nf < 4; nf++) {
                    uint32_t b0 = b[nf >> 1][(nf & 1) * 2];
                    uint32_t b1 = b[nf >> 1][(nf & 1) * 2 + 1];
                    MMA_F16(acc[mf][nf], a[mf][0], a[mf][1], a[mf][2], a[mf][3], b0, b1);
                }
            // residual pass: Al x Bh (B frags reused)
#pragma unroll
            for (int mf = 0; mf < 2; mf++) {
                uint32_t addr = albase + aoff[mf] + (uint32_t)(((2 * ks + a_gsel) ^ lr) << 4);
                LDSM_X4(a[mf][0], a[mf][1], a[mf][2], a[mf][3], addr);
            }
#pragma unroll
            for (int mf = 0; mf < 2; mf++)
#pragma unroll
                for (int nf = 0; nf < 4; nf++) {
                    uint32_t b0 = b[nf >> 1][(nf & 1) * 2];
                    uint32_t b1 = b[nf >> 1][(nf & 1) * 2 + 1];
                    MMA_F16(acc[mf][nf], a[mf][0], a[mf][1], a[mf][2], a[mf][3], b0, b1);
                }
        }
    }

    int gid = lane >> 2, tig = lane & 3;
#pragma unroll
    for (int mf = 0; mf < 2; mf++) {
#pragma unroll
        for (int nf = 0; nf < 4; nf++) {
            int row0 = bm0 + wm * 32 + mf * 16 + gid;
            int col = bn0 + wn * 32 + nf * 8 + tig * 2;
            float bx = __ldg(&bias[col]);
            float by = __ldg(&bias[col + 1]);
            float v00 = fmaxf(acc[mf][nf][0] + bx, 0.f);
            float v01 = fmaxf(acc[mf][nf][1] + by, 0.f);
            float v10 = fmaxf(acc[mf][nf][2] + bx, 0.f);
            float v11 = fmaxf(acc[mf][nf][3] + by, 0.f);
            if (mode == 0) {
                *reinterpret_cast<float2*>(&Cf[(size_t)row0 * DDIM + col]) = make_float2(v00, v01);
                *reinterpret_cast<float2*>(&Cf[(size_t)(row0 + 8) * DDIM + col]) = make_float2(v10, v11);
            } else {
                __half h0, l0, h1, l1;
                split2h(v00, h0, l0); split2h(v01, h1, l1);
                *reinterpret_cast<__half2*>(&Ch[(size_t)row0 * DDIM + col]) = __halves2half2(h0, h1);
                *reinterpret_cast<__half2*>(&Cl[(size_t)row0 * DDIM + col]) = __halves2half2(l0, l1);
                split2h(v10, h0, l0); split2h(v11, h1, l1);
                *reinterpret_cast<__half2*>(&Ch[(size_t)(row0 + 8) * DDIM + col]) = __halves2half2(h0, h1);
                *reinterpret_cast<__half2*>(&Cl[(size_t)(row0 + 8) * DDIM + col]) = __halves2half2(l0, l1);
            }
        }
    }
}

// ---------------------------------------------------------------------------
// Heads split-K GEMM
// ---------------------------------------------------------------------------
__global__ __launch_bounds__(256) void heads_partial(const float* __restrict__ w8c,
                                                     const float* __restrict__ w8d) {
    __shared__ float As[32][132];
    __shared__ float Bs[32][48];
    int r0 = blockIdx.x * 128;
    int ks = blockIdx.y;
    int k0 = ks * 512;
    int t = threadIdx.x;
    int ty = t >> 3, tx = t & 7;

    float acc[4][6];
#pragma unroll
    for (int i = 0; i < 4; i++)
#pragma unroll
        for (int j = 0; j < 6; j++) acc[i][j] = 0.f;

    for (int kc = 0; kc < 512; kc += 32) {
        for (int f = t; f < 1024; f += 256) {
            int r = f >> 3, q = f & 7;
            float4 v = *reinterpret_cast<const float4*>(&g_h2[(size_t)(r0 + r) * DDIM + k0 + kc + q * 4]);
            As[q * 4 + 0][r] = v.x; As[q * 4 + 1][r] = v.y;
            As[q * 4 + 2][r] = v.z; As[q * 4 + 3][r] = v.w;
        }
        for (int f = t; f < 336; f += 256) {
            int c = f >> 3, q = f & 7;
            const float* wr = (c < 21) ? (w8c + (size_t)c * DDIM) : (w8d + (size_t)(c - 21) * DDIM);
            float4 v = *reinterpret_cast<const float4*>(wr + k0 + kc + q * 4);
            Bs[q * 4 + 0][c] = v.x; Bs[q * 4 + 1][c] = v.y;
            Bs[q * 4 + 2][c] = v.z; Bs[q * 4 + 3][c] = v.w;
        }
        __syncthreads();
#pragma unroll
        for (int kk = 0; kk < 32; kk++) {
            float a[4], b[6];
#pragma unroll
            for (int i = 0; i < 4; i++) a[i] = As[kk][ty * 4 + i];
#pragma unroll
            for (int j = 0; j < 6; j++) b[j] = Bs[kk][tx * 6 + j];
#pragma unroll
            for (int i = 0; i < 4; i++)
#pragma unroll
                for (int j = 0; j < 6; j++) acc[i][j] = fmaf(a[i], b[j], acc[i][j]);
        }
        __syncthreads();
    }
#pragma unroll
    for (int i = 0; i < 4; i++) {
        int r = r0 + ty * 4 + i;
#pragma unroll
        for (int j = 0; j < 6; j++) {
            g_hpart[(size_t)ks * R_ROIS * 48 + (size_t)r * 48 + tx * 6 + j] = acc[i][j];
        }
    }
}

__global__ __launch_bounds__(256) void heads_reduce(const float* __restrict__ b8c,
                                                    const float* __restrict__ b8d) {
    int i = blockIdx.x * 256 + threadIdx.x;
    if (i >= R_ROIS * 42) return;
    int r = i / 42, c = i - r * 42;
    float s = 0.f;
#pragma unroll
    for (int ks = 0; ks < 8; ks++) s += g_hpart[(size_t)ks * R_ROIS * 48 + (size_t)r * 48 + c];
    if (c < 21) g_xc[r * NCLS + c] = fmaxf(s + b8c[c], 0.f);
    else        g_xd[r * NCLS + (c - 21)] = fmaxf(s + b8d[c - 21], 0.f);
}

// ---------------------------------------------------------------------------
// Softmax epilogue
// ---------------------------------------------------------------------------
__global__ __launch_bounds__(256) void colstats_kernel() {
    __shared__ float red[256];
    int c = blockIdx.x;
    int t = threadIdx.x;
    float m = -INFINITY;
    for (int r = t; r < R_ROIS; r += 256) m = fmaxf(m, g_xd[r * NCLS + c]);
    red[t] = m;
    __syncthreads();
    for (int s = 128; s; s >>= 1) {
        if (t < s) red[t] = fmaxf(red[t], red[t + s]);
        __syncthreads();
    }
    float cm = red[0];
    __syncthreads();
    float s2 = 0.f;
    for (int r = t; r < R_ROIS; r += 256) s2 += expf(g_xd[r * NCLS + c] - cm);
    red[t] = s2;
    __syncthreads();
    for (int s = 128; s; s >>= 1) {
        if (t < s) red[t] += red[t + s];
        __syncthreads();
    }
    if (t == 0) { g_colmax[c] = cm; g_colsum[c] = red[0]; }
}

__global__ __launch_bounds__(256) void finalize_kernel(float* __restrict__ out) {
    int warp = threadIdx.x >> 5;
    int lane = threadIdx.x & 31;
    int r = blockIdx.x * 8 + warp;
    if (r >= R_ROIS) return;

    float v = (lane < NCLS) ? g_xc[r * NCLS + lane] : -INFINITY;
    float m = v;
#pragma unroll
    for (int off = 16; off; off >>= 1) m = fmaxf(m, __shfl_xor_sync(0xFFFFFFFFu, m, off));
    float e = (lane < NCLS) ? expf(v - m) : 0.f;
    float s = e;
#pragma unroll
    for (int off = 16; off; off >>= 1) s += __shfl_xor_sync(0xFFFFFFFFu, s, off);

    if (lane < NCLS) {
        float dr = e / s;
        float smd = expf(g_xd[r * NCLS + lane] - g_colmax[lane]) / g_colsum[lane];
        out[OUT_DM + r * NCLS + lane] = dr * smd;
        out[OUT_DR + r * NCLS + lane] = dr;
    }
}

__global__ __launch_bounds__(256) void score_kernel(const float* __restrict__ dm,
                                                    float* __restrict__ score) {
    __shared__ float red[256];
    int c = blockIdx.x;
    int t = threadIdx.x;
    float s = 0.f;
    for (int r = t; r < R_ROIS; r += 256) s += dm[r * NCLS + c];
    red[t] = s;
    __syncthreads();
    for (int st = 128; st; st >>= 1) {
        if (t < st) red[t] += red[t + st];
        __syncthreads();
    }
    if (t == 0) score[c] = red[0];
}

// ---------------------------------------------------------------------------
// Launch — FC6 is the 4th launch (profiler capture slot)
// ---------------------------------------------------------------------------
extern "C" void kernel_launch(void* const* d_in, const int* in_sizes, int n_in,
                              void* d_out, int out_size) {
    const float* x   = (const float*)d_in[0];
    const float* w6  = (const float*)d_in[1];
    const float* b6  = (const float*)d_in[2];
    const float* w7  = (const float*)d_in[3];
    const float* b7  = (const float*)d_in[4];
    const float* w8c = (const float*)d_in[5];
    const float* b8c = (const float*)d_in[6];
    const float* w8d = (const float*)d_in[7];
    const float* b8d = (const float*)d_in[8];
    const int*   ssw = (const int*)d_in[9];
    float* out = (float*)d_out;

    __half *p_yh, *p_yl, *p_w6h, *p_w7h, *p_h1h, *p_h1l;
    float *p_h2;
    cudaGetSymbolAddress((void**)&p_yh, g_yh);
    cudaGetSymbolAddress((void**)&p_yl, g_yl);
    cudaGetSymbolAddress((void**)&p_w6h, g_w6h);
    cudaGetSymbolAddress((void**)&p_w7h, g_w7h);
    cudaGetSymbolAddress((void**)&p_h1h, g_h1h);
    cudaGetSymbolAddress((void**)&p_h1l, g_h1l);
    cudaGetSymbolAddress((void**)&p_h2, g_h2);

    cudaFuncSetAttribute(gemm_mma, cudaFuncAttributeMaxDynamicSharedMemorySize, GEMM_SMEM);
    cudaFuncSetAttribute(pool_kernel, cudaFuncAttributeMaxDynamicSharedMemorySize, POOL_SMEM);

    // 1) FC6 weight prep
    wsum_h_kernel<<<(DDIM * KHALF / 4 + 255) / 256, 256>>>(w6);

    // 2) fused SPP pool
    {
        dim3 grid(NORI, CCH / 32);
        pool_kernel<<<grid, 256, POOL_SMEM>>>(x);
    }

    // 3) SPP gather
    spp_gather_kernel<<<R_ROIS, 256>>>(ssw);

    // 4) FC6 (fp16x2): h1 = relu(y·wsum6^T + b6) -> fp16 hi/lo  [profiled]
    {
        dim3 grid(DDIM / 64, R_ROIS / 64);
        gemm_mma<<<grid, 128, GEMM_SMEM>>>(p_yh, p_yl, p_w6h, b6, KHALF, 1,
                                           nullptr, p_h1h, p_h1l);
    }

    // 5) FC7 weight prep
    w7_h_kernel<<<(DDIM * DDIM / 4 + 255) / 256, 256>>>(w7);

    // 6) FC7: h2 = relu(h1·w7^T + b7) -> fp32
    {
        dim3 grid(DDIM / 64, R_ROIS / 64);
        gemm_mma<<<grid, 128, GEMM_SMEM>>>(p_h1h, p_h1l, p_w7h, b7, DDIM, 0,
                                           p_h2, nullptr, nullptr);
    }

    // 7) heads
    {
        dim3 grid(R_ROIS / 128, 8);
        heads_partial<<<grid, 256>>>(w8c, w8d);
        heads_reduce<<<(R_ROIS * 42 + 255) / 256, 256>>>(b8c, b8d);
    }

    // 8) softmax stats + finalize + score
    colstats_kernel<<<NCLS, 256>>>();
    finalize_kernel<<<R_ROIS / 8, 256>>>(out);
    score_kernel<<<NCLS, 256>>>(out + OUT_DM, out + OUT_SC);
}

// round 13
// speedup vs baseline: 1.0219x; 1.0219x over previous
#include <cuda_runtime.h>
#include <cuda_fp16.h>
#include <math.h>
#include <stdint.h>

// ---------------------------------------------------------------------------
// Problem constants
// ---------------------------------------------------------------------------
#define R_ROIS 2048
#define CCH    512
#define HWDIM  64
#define DDIM   4096
#define NCLS   21
#define KHALF  2048
#define NORI   58

#define OUT_DM 0
#define OUT_DR (R_ROIS * NCLS)
#define OUT_SC (2 * R_ROIS * NCLS)

// ---------------------------------------------------------------------------
// Scratch (device globals)
// ---------------------------------------------------------------------------
__device__ float g_vmax[NORI * NORI * CCH];
__device__ __half g_yh[R_ROIS * KHALF];
__device__ __half g_yl[R_ROIS * KHALF];
__device__ __half g_w6h[DDIM * KHALF];
__device__ __half g_w7h[DDIM * DDIM];
__device__ __half g_h1h[R_ROIS * DDIM];
__device__ __half g_h1l[R_ROIS * DDIM];
__device__ float g_h2[R_ROIS * DDIM];
__device__ float g_hpart[8 * R_ROIS * 48];
__device__ float g_xc[R_ROIS * NCLS];
__device__ float g_xd[R_ROIS * NCLS];
__device__ float g_colmax[NCLS];
__device__ float g_colsum[NCLS];

// ---------------------------------------------------------------------------
// Helpers
// ---------------------------------------------------------------------------
__device__ __forceinline__ uint32_t smem_u32(const void* p) {
    uint32_t a;
    asm("{ .reg .u64 t; cvta.to.shared.u64 t, %1; cvt.u32.u64 %0, t; }" : "=r"(a) : "l"(p));
    return a;
}

__device__ __forceinline__ void split2h(float v, __half& h, __half& l) {
    h = __float2half_rn(v);
    l = __float2half_rn(v - __half2float(h));
}

__device__ __forceinline__ uint32_t swz(int r, int g) {
    return (uint32_t)(r >> 3) * 1024u + (uint32_t)(r & 7) * 128u
         + (uint32_t)((g ^ (r & 7)) << 4);
}

#define CP_ASYNC16(dst, src) \
    asm volatile("cp.async.cg.shared.global [%0], [%1], 16;" :: "r"(dst), "l"(src))
#define CP_COMMIT() asm volatile("cp.async.commit_group;" ::: "memory")
#define CP_WAIT1()  asm volatile("cp.async.wait_group 1;" ::: "memory")

#define LDSM_X4(r0, r1, r2, r3, addr) \
    asm volatile("ldmatrix.sync.aligned.m8n8.x4.shared.b16 {%0,%1,%2,%3}, [%4];" \
                 : "=r"(r0), "=r"(r1), "=r"(r2), "=r"(r3) : "r"(addr))

#define MMA_F16(c, a0, a1, a2, a3, b0, b1) \
    asm volatile("mma.sync.aligned.m16n8k16.row.col.f32.f16.f16.f32 " \
                 "{%0,%1,%2,%3}, {%4,%5,%6,%7}, {%8,%9}, {%0,%1,%2,%3};" \
                 : "+f"((c)[0]), "+f"((c)[1]), "+f"((c)[2]), "+f"((c)[3]) \
                 : "r"(a0), "r"(a1), "r"(a2), "r"(a3), "r"(b0), "r"(b1))

// ---------------------------------------------------------------------------
// Fused SPP pool
// ---------------------------------------------------------------------------
#define POOL_SMEM (32 * 7 * 61 * 4)

__global__ __launch_bounds__(256) void pool_kernel(const float* __restrict__ x) {
    extern __shared__ float hm[];
    int yp = blockIdx.x;
    int cg = blockIdx.y;
    int t = threadIdx.x;

    for (int idx = t; idx < 32 * 7 * NORI; idx += 256) {
        int xp = idx % NORI;
        int cy = idx / NORI;
        int y = cy % 7, c = cy / 7;
        const float* src = x + ((size_t)(cg * 32 + c) * HWDIM + (yp + y)) * HWDIM + xp;
        float m = src[0];
#pragma unroll
        for (int d = 1; d < 7; d++) m = fmaxf(m, src[d]);
        hm[cy * 61 + xp] = m;
    }
    __syncthreads();

    for (int idx = t; idx < NORI * 32; idx += 256) {
        int c = idx & 31;
        int xp = idx >> 5;
        float m = hm[(c * 7) * 61 + xp];
#pragma unroll
        for (int y = 1; y < 7; y++) m = fmaxf(m, hm[(c * 7 + y) * 61 + xp]);
        g_vmax[((size_t)yp * NORI + xp) * CCH + cg * 32 + c] = m;
    }
}

// ---------------------------------------------------------------------------
// SPP gather
// ---------------------------------------------------------------------------
__global__ __launch_bounds__(256) void spp_gather_kernel(const int* __restrict__ ssw) {
    __shared__ float ys[KHALF];
    int r = blockIdx.x;
    int y0 = ssw[r * 4 + 0];
    int x0 = ssw[r * 4 + 1];
    int t = threadIdx.x;
#pragma unroll
    for (int q = 0; q < 4; q++) {
        int i = q >> 1, j = q & 1;
        const float* src = g_vmax + ((size_t)(y0 + 7 * i) * NORI + (x0 + 7 * j)) * CCH;
        for (int c0 = 0; c0 < CCH; c0 += 256) {
            int c = c0 + t;
            ys[c * 4 + q] = src[c];
        }
    }
    __syncthreads();
    int k0 = t * 8;
    __half hv[8], lv[8];
#pragma unroll
    for (int u = 0; u < 8; u++) split2h(ys[k0 + u], hv[u], lv[u]);
    *reinterpret_cast<uint4*>(&g_yh[(size_t)r * KHALF + k0]) = *reinterpret_cast<uint4*>(hv);
    *reinterpret_cast<uint4*>(&g_yl[(size_t)r * KHALF + k0]) = *reinterpret_cast<uint4*>(lv);
}

// ---------------------------------------------------------------------------
// Weight fold + fp16 conversion
// ---------------------------------------------------------------------------
__global__ __launch_bounds__(256) void wsum_h_kernel(const float* __restrict__ w6) {
    int t = blockIdx.x * blockDim.x + threadIdx.x;
    const int NQ = DDIM * KHALF / 4;
    if (t >= NQ) return;
    int e = t / (KHALF / 4);
    int kq = t - e * (KHALF / 4);
    float4 av = reinterpret_cast<const float4*>(w6 + (size_t)e * DDIM)[kq];
    float4 bv = reinterpret_cast<const float4*>(w6 + (size_t)e * DDIM + KHALF)[kq];
    __half hv[4];
    hv[0] = __float2half_rn(av.x + bv.x);
    hv[1] = __float2half_rn(av.y + bv.y);
    hv[2] = __float2half_rn(av.z + bv.z);
    hv[3] = __float2half_rn(av.w + bv.w);
    *reinterpret_cast<uint2*>(&g_w6h[(size_t)e * KHALF + kq * 4]) = *reinterpret_cast<uint2*>(hv);
}

__global__ __launch_bounds__(256) void w7_h_kernel(const float* __restrict__ w7) {
    int t = blockIdx.x * blockDim.x + threadIdx.x;
    const int NQ = DDIM * DDIM / 4;
    if (t >= NQ) return;
    float4 v = reinterpret_cast<const float4*>(w7)[t];
    __half hv[4];
    hv[0] = __float2half_rn(v.x);
    hv[1] = __float2half_rn(v.y);
    hv[2] = __float2half_rn(v.z);
    hv[3] = __float2half_rn(v.w);
    *reinterpret_cast<uint2*>(&g_w7h[(size_t)t * 4]) = *reinterpret_cast<uint2*>(hv);
}

// ---------------------------------------------------------------------------
// GEMM variant A (FC6): CTA 64x64, 3 CTAs/SM, stage 24KB x3.
// ---------------------------------------------------------------------------
#define STG64 24576
#define SMEM64 (3 * STG64)

__device__ __forceinline__ void load_stage64(
    const __half* __restrict__ Ah, const __half* __restrict__ Al,
    const __half* __restrict__ Bh,
    int Kb, int bm0, int bn0, int k0, uint32_t sbase, int tid) {
#pragma unroll
    for (int it = 0; it < 12; it++) {
        int f = tid + it * 128;
        const __half* src;
        uint32_t dst;
        if (f < 512) {
            int r = f >> 3, g = f & 7;
            src = Ah + (size_t)(bm0 + r) * Kb + k0 + g * 8;
            dst = sbase + swz(r, g);
        } else if (f < 1024) {
            int fl = f - 512;
            int r = fl >> 3, g = fl & 7;
            src = Al + (size_t)(bm0 + r) * Kb + k0 + g * 8;
            dst = sbase + 8192u + swz(r, g);
        } else {
            int fl = f - 1024;
            int r = fl >> 3, g = fl & 7;
            src = Bh + (size_t)(bn0 + r) * Kb + k0 + g * 8;
            dst = sbase + 16384u + swz(r, g);
        }
        CP_ASYNC16(dst, src);
    }
}

__global__ __launch_bounds__(128, 3) void gemm_mma64(
    const __half* __restrict__ Ah, const __half* __restrict__ Al,
    const __half* __restrict__ Bh,
    const float* __restrict__ bias, int Kb,
    __half* __restrict__ Ch, __half* __restrict__ Cl) {
    extern __shared__ __align__(128) char smp[];
    uint32_t s0 = smem_u32(smp);

    int tid = threadIdx.x;
    int wid = tid >> 5;
    int lane = tid & 31;
    int wm = wid & 1;
    int wn = wid >> 1;
    int bm0 = blockIdx.y * 64;
    int bn0 = blockIdx.x * 64;

    int lr = lane & 7;
    int a_add8 = (lane >> 3) & 1;
    int a_gsel = lane >> 4;
    int b_add8 = lane >> 4;
    int b_gsel = (lane >> 3) & 1;

    uint32_t aoff[2], boff[2];
#pragma unroll
    for (int mf = 0; mf < 2; mf++)
        aoff[mf] = (uint32_t)(wm * 4 + mf * 2 + a_add8) * 1024u + (uint32_t)lr * 128u;
#pragma unroll
    for (int nf2 = 0; nf2 < 2; nf2++)
        boff[nf2] = (uint32_t)(wn * 4 + nf2 * 2 + b_add8) * 1024u + (uint32_t)lr * 128u;

    float acc[2][4][4];
#pragma unroll
    for (int i = 0; i < 2; i++)
#pragma unroll
        for (int j = 0; j < 4; j++)
#pragma unroll
            for (int q = 0; q < 4; q++) acc[i][j][q] = 0.f;

    int nch = Kb >> 6;

    load_stage64(Ah, Al, Bh, Kb, bm0, bn0, 0, s0, tid);
    CP_COMMIT();
    load_stage64(Ah, Al, Bh, Kb, bm0, bn0, 64, s0 + STG64, tid);
    CP_COMMIT();

    for (int kb = 0; kb < nch; kb++) {
        CP_WAIT1();
        __syncthreads();

        int nk = kb + 2;
        if (nk < nch) {
            load_stage64(Ah, Al, Bh, Kb, bm0, bn0, nk * 64,
                         s0 + (uint32_t)(nk % 3) * STG64, tid);
        }
        CP_COMMIT();

        uint32_t abase = s0 + (uint32_t)(kb % 3) * STG64;
        uint32_t albase = abase + 8192u;
        uint32_t bbase = abase + 16384u;

#pragma unroll
        for (int ks = 0; ks < 4; ks++) {
            uint32_t b[2][4];
#pragma unroll
            for (int nf2 = 0; nf2 < 2; nf2++) {
                uint32_t addr = bbase + boff[nf2] + (uint32_t)(((2 * ks + b_gsel) ^ lr) << 4);
                LDSM_X4(b[nf2][0], b[nf2][1], b[nf2][2], b[nf2][3], addr);
            }
            uint32_t a[2][4];
#pragma unroll
            for (int mf = 0; mf < 2; mf++) {
                uint32_t addr = abase + aoff[mf] + (uint32_t)(((2 * ks + a_gsel) ^ lr) << 4);
                LDSM_X4(a[mf][0], a[mf][1], a[mf][2], a[mf][3], addr);
            }
#pragma unroll
            for (int mf = 0; mf < 2; mf++)
#pragma unroll
                for (int nf = 0; nf < 4; nf++) {
                    uint32_t b0 = b[nf >> 1][(nf & 1) * 2];
                    uint32_t b1 = b[nf >> 1][(nf & 1) * 2 + 1];
                    MMA_F16(acc[mf][nf], a[mf][0], a[mf][1], a[mf][2], a[mf][3], b0, b1);
                }
#pragma unroll
            for (int mf = 0; mf < 2; mf++) {
                uint32_t addr = albase + aoff[mf] + (uint32_t)(((2 * ks + a_gsel) ^ lr) << 4);
                LDSM_X4(a[mf][0], a[mf][1], a[mf][2], a[mf][3], addr);
            }
#pragma unroll
            for (int mf = 0; mf < 2; mf++)
#pragma unroll
                for (int nf = 0; nf < 4; nf++) {
                    uint32_t b0 = b[nf >> 1][(nf & 1) * 2];
                    uint32_t b1 = b[nf >> 1][(nf & 1) * 2 + 1];
                    MMA_F16(acc[mf][nf], a[mf][0], a[mf][1], a[mf][2], a[mf][3], b0, b1);
                }
        }
    }

    int gid = lane >> 2, tig = lane & 3;
#pragma unroll
    for (int mf = 0; mf < 2; mf++) {
#pragma unroll
        for (int nf = 0; nf < 4; nf++) {
            int row0 = bm0 + wm * 32 + mf * 16 + gid;
            int col = bn0 + wn * 32 + nf * 8 + tig * 2;
            float bx = __ldg(&bias[col]);
            float by = __ldg(&bias[col + 1]);
            float v00 = fmaxf(acc[mf][nf][0] + bx, 0.f);
            float v01 = fmaxf(acc[mf][nf][1] + by, 0.f);
            float v10 = fmaxf(acc[mf][nf][2] + bx, 0.f);
            float v11 = fmaxf(acc[mf][nf][3] + by, 0.f);
            __half h0, l0, h1, l1;
            split2h(v00, h0, l0); split2h(v01, h1, l1);
            *reinterpret_cast<__half2*>(&Ch[(size_t)row0 * DDIM + col]) = __halves2half2(h0, h1);
            *reinterpret_cast<__half2*>(&Cl[(size_t)row0 * DDIM + col]) = __halves2half2(l0, l1);
            split2h(v10, h0, l0); split2h(v11, h1, l1);
            *reinterpret_cast<__half2*>(&Ch[(size_t)(row0 + 8) * DDIM + col]) = __halves2half2(h0, h1);
            *reinterpret_cast<__half2*>(&Cl[(size_t)(row0 + 8) * DDIM + col]) = __halves2half2(l0, l1);
        }
    }
}

// ---------------------------------------------------------------------------
// GEMM variant B (FC7): CTA 64x128, 2 CTAs/SM, stage 32KB x3.
// ---------------------------------------------------------------------------
#define STG128 32768
#define SMEM128 (3 * STG128)

__device__ __forceinline__ void load_stage128(
    const __half* __restrict__ Ah, const __half* __restrict__ Al,
    const __half* __restrict__ Bh,
    int Kb, int bm0, int bn0, int k0, uint32_t sbase, int tid) {
#pragma unroll
    for (int it = 0; it < 16; it++) {
        int f = tid + it * 128;
        const __half* src;
        uint32_t dst;
        if (f < 512) {
            int r = f >> 3, g = f & 7;
            src = Ah + (size_t)(bm0 + r) * Kb + k0 + g * 8;
            dst = sbase + swz(r, g);
        } else if (f < 1024) {
            int fl = f - 512;
            int r = fl >> 3, g = fl & 7;
            src = Al + (size_t)(bm0 + r) * Kb + k0 + g * 8;
            dst = sbase + 8192u + swz(r, g);
        } else {
            int fl = f - 1024;
            int r = fl >> 3, g = fl & 7;
            src = Bh + (size_t)(bn0 + r) * Kb + k0 + g * 8;
            dst = sbase + 16384u + swz(r, g);
        }
        CP_ASYNC16(dst, src);
    }
}

__global__ __launch_bounds__(128, 2) void gemm_mma128(
    const __half* __restrict__ Ah, const __half* __restrict__ Al,
    const __half* __restrict__ Bh,
    const float* __restrict__ bias, int Kb,
    float* __restrict__ Cf) {
    extern __shared__ __align__(128) char smp[];
    uint32_t s0 = smem_u32(smp);

    int tid = threadIdx.x;
    int wid = tid >> 5;
    int lane = tid & 31;
    int wm = wid & 1;
    int wn = wid >> 1;
    int bm0 = blockIdx.y * 64;
    int bn0 = blockIdx.x * 128;

    int lr = lane & 7;
    int a_add8 = (lane >> 3) & 1;
    int a_gsel = lane >> 4;
    int b_add8 = lane >> 4;
    int b_gsel = (lane >> 3) & 1;

    uint32_t aoff[2], boff[4];
#pragma unroll
    for (int mf = 0; mf < 2; mf++)
        aoff[mf] = (uint32_t)(wm * 4 + mf * 2 + a_add8) * 1024u + (uint32_t)lr * 128u;
#pragma unroll
    for (int nf2 = 0; nf2 < 4; nf2++)
        boff[nf2] = (uint32_t)(wn * 8 + nf2 * 2 + b_add8) * 1024u + (uint32_t)lr * 128u;

    float acc[2][8][4];
#pragma unroll
    for (int i = 0; i < 2; i++)
#pragma unroll
        for (int j = 0; j < 8; j++)
#pragma unroll
            for (int q = 0; q < 4; q++) acc[i][j][q] = 0.f;

    int nch = Kb >> 6;

    load_stage128(Ah, Al, Bh, Kb, bm0, bn0, 0, s0, tid);
    CP_COMMIT();
    load_stage128(Ah, Al, Bh, Kb, bm0, bn0, 64, s0 + STG128, tid);
    CP_COMMIT();

    for (int kb = 0; kb < nch; kb++) {
        CP_WAIT1();
        __syncthreads();

        int nk = kb + 2;
        if (nk < nch) {
            load_stage128(Ah, Al, Bh, Kb, bm0, bn0, nk * 64,
                          s0 + (uint32_t)(nk % 3) * STG128, tid);
        }
        CP_COMMIT();

        uint32_t abase = s0 + (uint32_t)(kb % 3) * STG128;
        uint32_t albase = abase + 8192u;
        uint32_t bbase = abase + 16384u;

#pragma unroll
        for (int ks = 0; ks < 4; ks++) {
            uint32_t b[4][4];
#pragma unroll
            for (int nf2 = 0; nf2 < 4; nf2++) {
                uint32_t addr = bbase + boff[nf2] + (uint32_t)(((2 * ks + b_gsel) ^ lr) << 4);
                LDSM_X4(b[nf2][0], b[nf2][1], b[nf2][2], b[nf2][3], addr);
            }
            uint32_t a[2][4];
#pragma unroll
            for (int mf = 0; mf < 2; mf++) {
                uint32_t addr = abase + aoff[mf] + (uint32_t)(((2 * ks + a_gsel) ^ lr) << 4);
                LDSM_X4(a[mf][0], a[mf][1], a[mf][2], a[mf][3], addr);
            }
#pragma unroll
            for (int mf = 0; mf < 2; mf++)
#pragma unroll
                for (int nf = 0; nf < 8; nf++) {
                    uint32_t b0 = b[nf >> 1][(nf & 1) * 2];
                    uint32_t b1 = b[nf >> 1][(nf & 1) * 2 + 1];
                    MMA_F16(acc[mf][nf], a[mf][0], a[mf][1], a[mf][2], a[mf][3], b0, b1);
                }
#pragma unroll
            for (int mf = 0; mf < 2; mf++) {
                uint32_t addr = albase + aoff[mf] + (uint32_t)(((2 * ks + a_gsel) ^ lr) << 4);
                LDSM_X4(a[mf][0], a[mf][1], a[mf][2], a[mf][3], addr);
            }
#pragma unroll
            for (int mf = 0; mf < 2; mf++)
#pragma unroll
                for (int nf = 0; nf < 8; nf++) {
                    uint32_t b0 = b[nf >> 1][(nf & 1) * 2];
                    uint32_t b1 = b[nf >> 1][(nf & 1) * 2 + 1];
                    MMA_F16(acc[mf][nf], a[mf][0], a[mf][1], a[mf][2], a[mf][3], b0, b1);
                }
        }
    }

    int gid = lane >> 2, tig = lane & 3;
#pragma unroll
    for (int mf = 0; mf < 2; mf++) {
#pragma unroll
        for (int nf = 0; nf < 8; nf++) {
            int row0 = bm0 + wm * 32 + mf * 16 + gid;
            int col = bn0 + wn * 64 + nf * 8 + tig * 2;
            float bx = __ldg(&bias[col]);
            float by = __ldg(&bias[col + 1]);
            float v00 = fmaxf(acc[mf][nf][0] + bx, 0.f);
            float v01 = fmaxf(acc[mf][nf][1] + by, 0.f);
            float v10 = fmaxf(acc[mf][nf][2] + bx, 0.f);
            float v11 = fmaxf(acc[mf][nf][3] + by, 0.f);
            *reinterpret_cast<float2*>(&Cf[(size_t)row0 * DDIM + col]) = make_float2(v00, v01);
            *reinterpret_cast<float2*>(&Cf[(size_t)(row0 + 8) * DDIM + col]) = make_float2(v10, v11);
        }
    }
}

// ---------------------------------------------------------------------------
// Heads split-K GEMM
// ---------------------------------------------------------------------------
__global__ __launch_bounds__(256) void heads_partial(const float* __restrict__ w8c,
                                                     const float* __restrict__ w8d) {
    __shared__ float As[32][132];
    __shared__ float Bs[32][48];
    int r0 = blockIdx.x * 128;
    int ks = blockIdx.y;
    int k0 = ks * 512;
    int t = threadIdx.x;
    int ty = t >> 3, tx = t & 7;

    float acc[4][6];
#pragma unroll
    for (int i = 0; i < 4; i++)
#pragma unroll
        for (int j = 0; j < 6; j++) acc[i][j] = 0.f;

    for (int kc = 0; kc < 512; kc += 32) {
        for (int f = t; f < 1024; f += 256) {
            int r = f >> 3, q = f & 7;
            float4 v = *reinterpret_cast<const float4*>(&g_h2[(size_t)(r0 + r) * DDIM + k0 + kc + q * 4]);
            As[q * 4 + 0][r] = v.x; As[q * 4 + 1][r] = v.y;
            As[q * 4 + 2][r] = v.z; As[q * 4 + 3][r] = v.w;
        }
        for (int f = t; f < 336; f += 256) {
            int c = f >> 3, q = f & 7;
            const float* wr = (c < 21) ? (w8c + (size_t)c * DDIM) : (w8d + (size_t)(c - 21) * DDIM);
            float4 v = *reinterpret_cast<const float4*>(wr + k0 + kc + q * 4);
            Bs[q * 4 + 0][c] = v.x; Bs[q * 4 + 1][c] = v.y;
            Bs[q * 4 + 2][c] = v.z; Bs[q * 4 + 3][c] = v.w;
        }
        __syncthreads();
#pragma unroll
        for (int kk = 0; kk < 32; kk++) {
            float a[4], b[6];
#pragma unroll
            for (int i = 0; i < 4; i++) a[i] = As[kk][ty * 4 + i];
#pragma unroll
            for (int j = 0; j < 6; j++) b[j] = Bs[kk][tx * 6 + j];
#pragma unroll
            for (int i = 0; i < 4; i++)
#pragma unroll
                for (int j = 0; j < 6; j++) acc[i][j] = fmaf(a[i], b[j], acc[i][j]);
        }
        __syncthreads();
    }
#pragma unroll
    for (int i = 0; i < 4; i++) {
        int r = r0 + ty * 4 + i;
#pragma unroll
        for (int j = 0; j < 6; j++) {
            g_hpart[(size_t)ks * R_ROIS * 48 + (size_t)r * 48 + tx * 6 + j] = acc[i][j];
        }
    }
}

__global__ __launch_bounds__(256) void heads_reduce(const float* __restrict__ b8c,
                                                    const float* __restrict__ b8d) {
    int i = blockIdx.x * 256 + threadIdx.x;
    if (i >= R_ROIS * 42) return;
    int r = i / 42, c = i - r * 42;
    float s = 0.f;
#pragma unroll
    for (int ks = 0; ks < 8; ks++) s += g_hpart[(size_t)ks * R_ROIS * 48 + (size_t)r * 48 + c];
    if (c < 21) g_xc[r * NCLS + c] = fmaxf(s + b8c[c], 0.f);
    else        g_xd[r * NCLS + (c - 21)] = fmaxf(s + b8d[c - 21], 0.f);
}

// ---------------------------------------------------------------------------
// Softmax epilogue
// ---------------------------------------------------------------------------
__global__ __launch_bounds__(256) void colstats_kernel() {
    __shared__ float red[256];
    int c = blockIdx.x;
    int t = threadIdx.x;
    float m = -INFINITY;
    for (int r = t; r < R_ROIS; r += 256) m = fmaxf(m, g_xd[r * NCLS + c]);
    red[t] = m;
    __syncthreads();
    for (int s = 128; s; s >>= 1) {
        if (t < s) red[t] = fmaxf(red[t], red[t + s]);
        __syncthreads();
    }
    float cm = red[0];
    __syncthreads();
    float s2 = 0.f;
    for (int r = t; r < R_ROIS; r += 256) s2 += expf(g_xd[r * NCLS + c] - cm);
    red[t] = s2;
    __syncthreads();
    for (int s = 128; s; s >>= 1) {
        if (t < s) red[t] += red[t + s];
        __syncthreads();
    }
    if (t == 0) { g_colmax[c] = cm; g_colsum[c] = red[0]; }
}

__global__ __launch_bounds__(256) void finalize_kernel(float* __restrict__ out) {
    int warp = threadIdx.x >> 5;
    int lane = threadIdx.x & 31;
    int r = blockIdx.x * 8 + warp;
    if (r >= R_ROIS) return;

    float v = (lane < NCLS) ? g_xc[r * NCLS + lane] : -INFINITY;
    float m = v;
#pragma unroll
    for (int off = 16; off; off >>= 1) m = fmaxf(m, __shfl_xor_sync(0xFFFFFFFFu, m, off));
    float e = (lane < NCLS) ? expf(v - m) : 0.f;
    float s = e;
#pragma unroll
    for (int off = 16; off; off >>= 1) s += __shfl_xor_sync(0xFFFFFFFFu, s, off);

    if (lane < NCLS) {
        float dr = e / s;
        float smd = expf(g_xd[r * NCLS + lane] - g_colmax[lane]) / g_colsum[lane];
        out[OUT_DM + r * NCLS + lane] = dr * smd;
        out[OUT_DR + r * NCLS + lane] = dr;
    }
}

__global__ __launch_bounds__(256) void score_kernel(const float* __restrict__ dm,
                                                    float* __restrict__ score) {
    __shared__ float red[256];
    int c = blockIdx.x;
    int t = threadIdx.x;
    float s = 0.f;
    for (int r = t; r < R_ROIS; r += 256) s += dm[r * NCLS + c];
    red[t] = s;
    __syncthreads();
    for (int st = 128; st; st >>= 1) {
        if (t < st) red[t] += red[t + st];
        __syncthreads();
    }
    if (t == 0) score[c] = red[0];
}

// ---------------------------------------------------------------------------
// Launch — single stream (stream fork violated allocation rules).
// Order keeps FC6 as launch #4 (profiler capture slot).
// ---------------------------------------------------------------------------
extern "C" void kernel_launch(void* const* d_in, const int* in_sizes, int n_in,
                              void* d_out, int out_size) {
    const float* x   = (const float*)d_in[0];
    const float* w6  = (const float*)d_in[1];
    const float* b6  = (const float*)d_in[2];
    const float* w7  = (const float*)d_in[3];
    const float* b7  = (const float*)d_in[4];
    const float* w8c = (const float*)d_in[5];
    const float* b8c = (const float*)d_in[6];
    const float* w8d = (const float*)d_in[7];
    const float* b8d = (const float*)d_in[8];
    const int*   ssw = (const int*)d_in[9];
    float* out = (float*)d_out;

    __half *p_yh, *p_yl, *p_w6h, *p_w7h, *p_h1h, *p_h1l;
    float *p_h2;
    cudaGetSymbolAddress((void**)&p_yh, g_yh);
    cudaGetSymbolAddress((void**)&p_yl, g_yl);
    cudaGetSymbolAddress((void**)&p_w6h, g_w6h);
    cudaGetSymbolAddress((void**)&p_w7h, g_w7h);
    cudaGetSymbolAddress((void**)&p_h1h, g_h1h);
    cudaGetSymbolAddress((void**)&p_h1l, g_h1l);
    cudaGetSymbolAddress((void**)&p_h2, g_h2);

    cudaFuncSetAttribute(gemm_mma64, cudaFuncAttributeMaxDynamicSharedMemorySize, SMEM64);
    cudaFuncSetAttribute(gemm_mma128, cudaFuncAttributeMaxDynamicSharedMemorySize, SMEM128);
    cudaFuncSetAttribute(pool_kernel, cudaFuncAttributeMaxDynamicSharedMemorySize, POOL_SMEM);

    // 1) FC6 weight prep
    wsum_h_kernel<<<(DDIM * KHALF / 4 + 255) / 256, 256>>>(w6);

    // 2) fused SPP pool
    {
        dim3 grid(NORI, CCH / 32);
        pool_kernel<<<grid, 256, POOL_SMEM>>>(x);
    }

    // 3) SPP gather
    spp_gather_kernel<<<R_ROIS, 256>>>(ssw);

    // 4) FC6 (64x64, 3 CTA/SM)  [profiled]
    {
        dim3 grid(DDIM / 64, R_ROIS / 64);
        gemm_mma64<<<grid, 128, SMEM64>>>(p_yh, p_yl, p_w6h, b6, KHALF, p_h1h, p_h1l);
    }

    // 5) FC7 weight prep
    w7_h_kernel<<<(DDIM * DDIM / 4 + 255) / 256, 256>>>(w7);

    // 6) FC7 (64x128, 2 CTA/SM)
    {
        dim3 grid(DDIM / 128, R_ROIS / 64);
        gemm_mma128<<<grid, 128, SMEM128>>>(p_h1h, p_h1l, p_w7h, b7, DDIM, p_h2);
    }

    // 7) heads
    {
        dim3 grid(R_ROIS / 128, 8);
        heads_partial<<<grid, 256>>>(w8c, w8d);
        heads_reduce<<<(R_ROIS * 42 + 255) / 256, 256>>>(b8c, b8d);
    }

    // 8) softmax stats + finalize + score
    colstats_kernel<<<NCLS, 256>>>();
    finalize_kernel<<<R_ROIS / 8, 256>>>(out);
    score_kernel<<<NCLS, 256>>>(out + OUT_DM, out + OUT_SC);
}

// round 14
// speedup vs baseline: 1.0889x; 1.0656x over previous
#include <cuda_runtime.h>
#include <cuda_fp16.h>
#include <math.h>
#include <stdint.h>

// ---------------------------------------------------------------------------
// Problem constants
// ---------------------------------------------------------------------------
#define R_ROIS 2048
#define CCH    512
#define HWDIM  64
#define DDIM   4096
#define NCLS   21
#define KHALF  2048
#define NORI   58

#define OUT_DM 0
#define OUT_DR (R_ROIS * NCLS)
#define OUT_SC (2 * R_ROIS * NCLS)

// ---------------------------------------------------------------------------
// Scratch (device globals)
// ---------------------------------------------------------------------------
__device__ float g_vmax[NORI * NORI * CCH];
__device__ __half g_yh[R_ROIS * KHALF];
__device__ __half g_yl[R_ROIS * KHALF];
__device__ __half g_w6h[DDIM * KHALF];
__device__ __half g_w7h[DDIM * DDIM];
__device__ __half g_h1h[R_ROIS * DDIM];
__device__ __half g_h1l[R_ROIS * DDIM];
__device__ float g_h2[R_ROIS * DDIM];
__device__ float g_hpart[8 * R_ROIS * 48];
__device__ float g_xc[R_ROIS * NCLS];
__device__ float g_xd[R_ROIS * NCLS];
__device__ float g_colmax[NCLS];
__device__ float g_colsum[NCLS];

// ---------------------------------------------------------------------------
// Helpers
// ---------------------------------------------------------------------------
__device__ __forceinline__ uint32_t smem_u32(const void* p) {
    uint32_t a;
    asm("{ .reg .u64 t; cvta.to.shared.u64 t, %1; cvt.u32.u64 %0, t; }" : "=r"(a) : "l"(p));
    return a;
}

__device__ __forceinline__ void split2h(float v, __half& h, __half& l) {
    h = __float2half_rn(v);
    l = __float2half_rn(v - __half2float(h));
}

__device__ __forceinline__ uint32_t swz(int r, int g) {
    return (uint32_t)(r >> 3) * 1024u + (uint32_t)(r & 7) * 128u
         + (uint32_t)((g ^ (r & 7)) << 4);
}

#define CP_ASYNC16(dst, src) \
    asm volatile("cp.async.cg.shared.global [%0], [%1], 16;" :: "r"(dst), "l"(src))
#define CP_COMMIT() asm volatile("cp.async.commit_group;" ::: "memory")
#define CP_WAIT1()  asm volatile("cp.async.wait_group 1;" ::: "memory")

#define LDSM_X4(r0, r1, r2, r3, addr) \
    asm volatile("ldmatrix.sync.aligned.m8n8.x4.shared.b16 {%0,%1,%2,%3}, [%4];" \
                 : "=r"(r0), "=r"(r1), "=r"(r2), "=r"(r3) : "r"(addr))

#define MMA_F16(c, a0, a1, a2, a3, b0, b1) \
    asm volatile("mma.sync.aligned.m16n8k16.row.col.f32.f16.f16.f32 " \
                 "{%0,%1,%2,%3}, {%4,%5,%6,%7}, {%8,%9}, {%0,%1,%2,%3};" \
                 : "+f"((c)[0]), "+f"((c)[1]), "+f"((c)[2]), "+f"((c)[3]) \
                 : "r"(a0), "r"(a1), "r"(a2), "r"(a3), "r"(b0), "r"(b1))

// ---------------------------------------------------------------------------
// Fused SPP pool
// ---------------------------------------------------------------------------
#define POOL_SMEM (32 * 7 * 61 * 4)

__global__ __launch_bounds__(256) void pool_kernel(const float* __restrict__ x) {
    extern __shared__ float hm[];
    int yp = blockIdx.x;
    int cg = blockIdx.y;
    int t = threadIdx.x;

    for (int idx = t; idx < 32 * 7 * NORI; idx += 256) {
        int xp = idx % NORI;
        int cy = idx / NORI;
        int y = cy % 7, c = cy / 7;
        const float* src = x + ((size_t)(cg * 32 + c) * HWDIM + (yp + y)) * HWDIM + xp;
        float m = src[0];
#pragma unroll
        for (int d = 1; d < 7; d++) m = fmaxf(m, src[d]);
        hm[cy * 61 + xp] = m;
    }
    __syncthreads();

    for (int idx = t; idx < NORI * 32; idx += 256) {
        int c = idx & 31;
        int xp = idx >> 5;
        float m = hm[(c * 7) * 61 + xp];
#pragma unroll
        for (int y = 1; y < 7; y++) m = fmaxf(m, hm[(c * 7 + y) * 61 + xp]);
        g_vmax[((size_t)yp * NORI + xp) * CCH + cg * 32 + c] = m;
    }
}

// ---------------------------------------------------------------------------
// SPP gather
// ---------------------------------------------------------------------------
__global__ __launch_bounds__(256) void spp_gather_kernel(const int* __restrict__ ssw) {
    __shared__ float ys[KHALF];
    int r = blockIdx.x;
    int y0 = ssw[r * 4 + 0];
    int x0 = ssw[r * 4 + 1];
    int t = threadIdx.x;
#pragma unroll
    for (int q = 0; q < 4; q++) {
        int i = q >> 1, j = q & 1;
        const float* src = g_vmax + ((size_t)(y0 + 7 * i) * NORI + (x0 + 7 * j)) * CCH;
        for (int c0 = 0; c0 < CCH; c0 += 256) {
            int c = c0 + t;
            ys[c * 4 + q] = src[c];
        }
    }
    __syncthreads();
    int k0 = t * 8;
    __half hv[8], lv[8];
#pragma unroll
    for (int u = 0; u < 8; u++) split2h(ys[k0 + u], hv[u], lv[u]);
    *reinterpret_cast<uint4*>(&g_yh[(size_t)r * KHALF + k0]) = *reinterpret_cast<uint4*>(hv);
    *reinterpret_cast<uint4*>(&g_yl[(size_t)r * KHALF + k0]) = *reinterpret_cast<uint4*>(lv);
}

// ---------------------------------------------------------------------------
// Weight fold + fp16 conversion
// ---------------------------------------------------------------------------
__global__ __launch_bounds__(256) void wsum_h_kernel(const float* __restrict__ w6) {
    int t = blockIdx.x * blockDim.x + threadIdx.x;
    const int NQ = DDIM * KHALF / 4;
    if (t >= NQ) return;
    int e = t / (KHALF / 4);
    int kq = t - e * (KHALF / 4);
    float4 av = reinterpret_cast<const float4*>(w6 + (size_t)e * DDIM)[kq];
    float4 bv = reinterpret_cast<const float4*>(w6 + (size_t)e * DDIM + KHALF)[kq];
    __half hv[4];
    hv[0] = __float2half_rn(av.x + bv.x);
    hv[1] = __float2half_rn(av.y + bv.y);
    hv[2] = __float2half_rn(av.z + bv.z);
    hv[3] = __float2half_rn(av.w + bv.w);
    *reinterpret_cast<uint2*>(&g_w6h[(size_t)e * KHALF + kq * 4]) = *reinterpret_cast<uint2*>(hv);
}

__global__ __launch_bounds__(256) void w7_h_kernel(const float* __restrict__ w7) {
    int t = blockIdx.x * blockDim.x + threadIdx.x;
    const int NQ = DDIM * DDIM / 4;
    if (t >= NQ) return;
    float4 v = reinterpret_cast<const float4*>(w7)[t];
    __half hv[4];
    hv[0] = __float2half_rn(v.x);
    hv[1] = __float2half_rn(v.y);
    hv[2] = __float2half_rn(v.z);
    hv[3] = __float2half_rn(v.w);
    *reinterpret_cast<uint2*>(&g_w7h[(size_t)t * 4]) = *reinterpret_cast<uint2*>(hv);
}

// ---------------------------------------------------------------------------
// GEMM variant A (FC6): CTA 64x64, 3 CTAs/SM, stage 24KB x3.
// Residual (Al) pass only for chunks kb < lo_nch (half-K correction).
// ---------------------------------------------------------------------------
#define STG64 24576
#define SMEM64 (3 * STG64)

__device__ __forceinline__ void load_stage64(
    const __half* __restrict__ Ah, const __half* __restrict__ Al,
    const __half* __restrict__ Bh,
    int Kb, int bm0, int bn0, int k0, uint32_t sbase, int tid, bool load_al) {
#pragma unroll
    for (int it = 0; it < 12; it++) {
        int f = tid + it * 128;
        const __half* src;
        uint32_t dst;
        if (f < 512) {
            int r = f >> 3, g = f & 7;
            src = Ah + (size_t)(bm0 + r) * Kb + k0 + g * 8;
            dst = sbase + swz(r, g);
        } else if (f < 1024) {
            if (!load_al) continue;
            int fl = f - 512;
            int r = fl >> 3, g = fl & 7;
            src = Al + (size_t)(bm0 + r) * Kb + k0 + g * 8;
            dst = sbase + 8192u + swz(r, g);
        } else {
            int fl = f - 1024;
            int r = fl >> 3, g = fl & 7;
            src = Bh + (size_t)(bn0 + r) * Kb + k0 + g * 8;
            dst = sbase + 16384u + swz(r, g);
        }
        CP_ASYNC16(dst, src);
    }
}

__global__ __launch_bounds__(128, 3) void gemm_mma64(
    const __half* __restrict__ Ah, const __half* __restrict__ Al,
    const __half* __restrict__ Bh,
    const float* __restrict__ bias, int Kb, int lo_nch,
    __half* __restrict__ Ch, __half* __restrict__ Cl) {
    extern __shared__ __align__(128) char smp[];
    uint32_t s0 = smem_u32(smp);

    int tid = threadIdx.x;
    int wid = tid >> 5;
    int lane = tid & 31;
    int wm = wid & 1;
    int wn = wid >> 1;
    int bm0 = blockIdx.y * 64;
    int bn0 = blockIdx.x * 64;

    int lr = lane & 7;
    int a_add8 = (lane >> 3) & 1;
    int a_gsel = lane >> 4;
    int b_add8 = lane >> 4;
    int b_gsel = (lane >> 3) & 1;

    uint32_t aoff[2], boff[2];
#pragma unroll
    for (int mf = 0; mf < 2; mf++)
        aoff[mf] = (uint32_t)(wm * 4 + mf * 2 + a_add8) * 1024u + (uint32_t)lr * 128u;
#pragma unroll
    for (int nf2 = 0; nf2 < 2; nf2++)
        boff[nf2] = (uint32_t)(wn * 4 + nf2 * 2 + b_add8) * 1024u + (uint32_t)lr * 128u;

    float acc[2][4][4];
#pragma unroll
    for (int i = 0; i < 2; i++)
#pragma unroll
        for (int j = 0; j < 4; j++)
#pragma unroll
            for (int q = 0; q < 4; q++) acc[i][j][q] = 0.f;

    int nch = Kb >> 6;

    load_stage64(Ah, Al, Bh, Kb, bm0, bn0, 0, s0, tid, 0 < lo_nch);
    CP_COMMIT();
    load_stage64(Ah, Al, Bh, Kb, bm0, bn0, 64, s0 + STG64, tid, 1 < lo_nch);
    CP_COMMIT();

    for (int kb = 0; kb < nch; kb++) {
        CP_WAIT1();
        __syncthreads();

        int nk = kb + 2;
        if (nk < nch) {
            load_stage64(Ah, Al, Bh, Kb, bm0, bn0, nk * 64,
                         s0 + (uint32_t)(nk % 3) * STG64, tid, nk < lo_nch);
        }
        CP_COMMIT();

        uint32_t abase = s0 + (uint32_t)(kb % 3) * STG64;
        uint32_t albase = abase + 8192u;
        uint32_t bbase = abase + 16384u;
        bool do_lo = (kb < lo_nch);

#pragma unroll
        for (int ks = 0; ks < 4; ks++) {
            uint32_t b[2][4];
#pragma unroll
            for (int nf2 = 0; nf2 < 2; nf2++) {
                uint32_t addr = bbase + boff[nf2] + (uint32_t)(((2 * ks + b_gsel) ^ lr) << 4);
                LDSM_X4(b[nf2][0], b[nf2][1], b[nf2][2], b[nf2][3], addr);
            }
            uint32_t a[2][4];
#pragma unroll
            for (int mf = 0; mf < 2; mf++) {
                uint32_t addr = abase + aoff[mf] + (uint32_t)(((2 * ks + a_gsel) ^ lr) << 4);
                LDSM_X4(a[mf][0], a[mf][1], a[mf][2], a[mf][3], addr);
            }
#pragma unroll
            for (int mf = 0; mf < 2; mf++)
#pragma unroll
                for (int nf = 0; nf < 4; nf++) {
                    uint32_t b0 = b[nf >> 1][(nf & 1) * 2];
                    uint32_t b1 = b[nf >> 1][(nf & 1) * 2 + 1];
                    MMA_F16(acc[mf][nf], a[mf][0], a[mf][1], a[mf][2], a[mf][3], b0, b1);
                }
            if (do_lo) {
#pragma unroll
                for (int mf = 0; mf < 2; mf++) {
                    uint32_t addr = albase + aoff[mf] + (uint32_t)(((2 * ks + a_gsel) ^ lr) << 4);
                    LDSM_X4(a[mf][0], a[mf][1], a[mf][2], a[mf][3], addr);
                }
#pragma unroll
                for (int mf = 0; mf < 2; mf++)
#pragma unroll
                    for (int nf = 0; nf < 4; nf++) {
                        uint32_t b0 = b[nf >> 1][(nf & 1) * 2];
                        uint32_t b1 = b[nf >> 1][(nf & 1) * 2 + 1];
                        MMA_F16(acc[mf][nf], a[mf][0], a[mf][1], a[mf][2], a[mf][3], b0, b1);
                    }
            }
        }
    }

    int gid = lane >> 2, tig = lane & 3;
#pragma unroll
    for (int mf = 0; mf < 2; mf++) {
#pragma unroll
        for (int nf = 0; nf < 4; nf++) {
            int row0 = bm0 + wm * 32 + mf * 16 + gid;
            int col = bn0 + wn * 32 + nf * 8 + tig * 2;
            float bx = __ldg(&bias[col]);
            float by = __ldg(&bias[col + 1]);
            float v00 = fmaxf(acc[mf][nf][0] + bx, 0.f);
            float v01 = fmaxf(acc[mf][nf][1] + by, 0.f);
            float v10 = fmaxf(acc[mf][nf][2] + bx, 0.f);
            float v11 = fmaxf(acc[mf][nf][3] + by, 0.f);
            __half h0, l0, h1, l1;
            split2h(v00, h0, l0); split2h(v01, h1, l1);
            *reinterpret_cast<__half2*>(&Ch[(size_t)row0 * DDIM + col]) = __halves2half2(h0, h1);
            *reinterpret_cast<__half2*>(&Cl[(size_t)row0 * DDIM + col]) = __halves2half2(l0, l1);
            split2h(v10, h0, l0); split2h(v11, h1, l1);
            *reinterpret_cast<__half2*>(&Ch[(size_t)(row0 + 8) * DDIM + col]) = __halves2half2(h0, h1);
            *reinterpret_cast<__half2*>(&Cl[(size_t)(row0 + 8) * DDIM + col]) = __halves2half2(l0, l1);
        }
    }
}

// ---------------------------------------------------------------------------
// GEMM variant B (FC7): CTA 64x128, 2 CTAs/SM, stage 32KB x3.
// Residual (Al) pass only for chunks kb < lo_nch.
// ---------------------------------------------------------------------------
#define STG128 32768
#define SMEM128 (3 * STG128)

__device__ __forceinline__ void load_stage128(
    const __half* __restrict__ Ah, const __half* __restrict__ Al,
    const __half* __restrict__ Bh,
    int Kb, int bm0, int bn0, int k0, uint32_t sbase, int tid, bool load_al) {
#pragma unroll
    for (int it = 0; it < 16; it++) {
        int f = tid + it * 128;
        const __half* src;
        uint32_t dst;
        if (f < 512) {
            int r = f >> 3, g = f & 7;
            src = Ah + (size_t)(bm0 + r) * Kb + k0 + g * 8;
            dst = sbase + swz(r, g);
        } else if (f < 1024) {
            if (!load_al) continue;
            int fl = f - 512;
            int r = fl >> 3, g = fl & 7;
            src = Al + (size_t)(bm0 + r) * Kb + k0 + g * 8;
            dst = sbase + 8192u + swz(r, g);
        } else {
            int fl = f - 1024;
            int r = fl >> 3, g = fl & 7;
            src = Bh + (size_t)(bn0 + r) * Kb + k0 + g * 8;
            dst = sbase + 16384u + swz(r, g);
        }
        CP_ASYNC16(dst, src);
    }
}

__global__ __launch_bounds__(128, 2) void gemm_mma128(
    const __half* __restrict__ Ah, const __half* __restrict__ Al,
    const __half* __restrict__ Bh,
    const float* __restrict__ bias, int Kb, int lo_nch,
    float* __restrict__ Cf) {
    extern __shared__ __align__(128) char smp[];
    uint32_t s0 = smem_u32(smp);

    int tid = threadIdx.x;
    int wid = tid >> 5;
    int lane = tid & 31;
    int wm = wid & 1;
    int wn = wid >> 1;
    int bm0 = blockIdx.y * 64;
    int bn0 = blockIdx.x * 128;

    int lr = lane & 7;
    int a_add8 = (lane >> 3) & 1;
    int a_gsel = lane >> 4;
    int b_add8 = lane >> 4;
    int b_gsel = (lane >> 3) & 1;

    uint32_t aoff[2], boff[4];
#pragma unroll
    for (int mf = 0; mf < 2; mf++)
        aoff[mf] = (uint32_t)(wm * 4 + mf * 2 + a_add8) * 1024u + (uint32_t)lr * 128u;
#pragma unroll
    for (int nf2 = 0; nf2 < 4; nf2++)
        boff[nf2] = (uint32_t)(wn * 8 + nf2 * 2 + b_add8) * 1024u + (uint32_t)lr * 128u;

    float acc[2][8][4];
#pragma unroll
    for (int i = 0; i < 2; i++)
#pragma unroll
        for (int j = 0; j < 8; j++)
#pragma unroll
            for (int q = 0; q < 4; q++) acc[i][j][q] = 0.f;

    int nch = Kb >> 6;

    load_stage128(Ah, Al, Bh, Kb, bm0, bn0, 0, s0, tid, 0 < lo_nch);
    CP_COMMIT();
    load_stage128(Ah, Al, Bh, Kb, bm0, bn0, 64, s0 + STG128, tid, 1 < lo_nch);
    CP_COMMIT();

    for (int kb = 0; kb < nch; kb++) {
        CP_WAIT1();
        __syncthreads();

        int nk = kb + 2;
        if (nk < nch) {
            load_stage128(Ah, Al, Bh, Kb, bm0, bn0, nk * 64,
                          s0 + (uint32_t)(nk % 3) * STG128, tid, nk < lo_nch);
        }
        CP_COMMIT();

        uint32_t abase = s0 + (uint32_t)(kb % 3) * STG128;
        uint32_t albase = abase + 8192u;
        uint32_t bbase = abase + 16384u;
        bool do_lo = (kb < lo_nch);

#pragma unroll
        for (int ks = 0; ks < 4; ks++) {
            uint32_t b[4][4];
#pragma unroll
            for (int nf2 = 0; nf2 < 4; nf2++) {
                uint32_t addr = bbase + boff[nf2] + (uint32_t)(((2 * ks + b_gsel) ^ lr) << 4);
                LDSM_X4(b[nf2][0], b[nf2][1], b[nf2][2], b[nf2][3], addr);
            }
            uint32_t a[2][4];
#pragma unroll
            for (int mf = 0; mf < 2; mf++) {
                uint32_t addr = abase + aoff[mf] + (uint32_t)(((2 * ks + a_gsel) ^ lr) << 4);
                LDSM_X4(a[mf][0], a[mf][1], a[mf][2], a[mf][3], addr);
            }
#pragma unroll
            for (int mf = 0; mf < 2; mf++)
#pragma unroll
                for (int nf = 0; nf < 8; nf++) {
                    uint32_t b0 = b[nf >> 1][(nf & 1) * 2];
                    uint32_t b1 = b[nf >> 1][(nf & 1) * 2 + 1];
                    MMA_F16(acc[mf][nf], a[mf][0], a[mf][1], a[mf][2], a[mf][3], b0, b1);
                }
            if (do_lo) {
#pragma unroll
                for (int mf = 0; mf < 2; mf++) {
                    uint32_t addr = albase + aoff[mf] + (uint32_t)(((2 * ks + a_gsel) ^ lr) << 4);
                    LDSM_X4(a[mf][0], a[mf][1], a[mf][2], a[mf][3], addr);
                }
#pragma unroll
                for (int mf = 0; mf < 2; mf++)
#pragma unroll
                    for (int nf = 0; nf < 8; nf++) {
                        uint32_t b0 = b[nf >> 1][(nf & 1) * 2];
                        uint32_t b1 = b[nf >> 1][(nf & 1) * 2 + 1];
                        MMA_F16(acc[mf][nf], a[mf][0], a[mf][1], a[mf][2], a[mf][3], b0, b1);
                    }
            }
        }
    }

    int gid = lane >> 2, tig = lane & 3;
#pragma unroll
    for (int mf = 0; mf < 2; mf++) {
#pragma unroll
        for (int nf = 0; nf < 8; nf++) {
            int row0 = bm0 + wm * 32 + mf * 16 + gid;
            int col = bn0 + wn * 64 + nf * 8 + tig * 2;
            float bx = __ldg(&bias[col]);
            float by = __ldg(&bias[col + 1]);
            float v00 = fmaxf(acc[mf][nf][0] + bx, 0.f);
            float v01 = fmaxf(acc[mf][nf][1] + by, 0.f);
            float v10 = fmaxf(acc[mf][nf][2] + bx, 0.f);
            float v11 = fmaxf(acc[mf][nf][3] + by, 0.f);
            *reinterpret_cast<float2*>(&Cf[(size_t)row0 * DDIM + col]) = make_float2(v00, v01);
            *reinterpret_cast<float2*>(&Cf[(size_t)(row0 + 8) * DDIM + col]) = make_float2(v10, v11);
        }
    }
}

// ---------------------------------------------------------------------------
// Heads split-K GEMM
// ---------------------------------------------------------------------------
__global__ __launch_bounds__(256) void heads_partial(const float* __restrict__ w8c,
                                                     const float* __restrict__ w8d) {
    __shared__ float As[32][132];
    __shared__ float Bs[32][48];
    int r0 = blockIdx.x * 128;
    int ks = blockIdx.y;
    int k0 = ks * 512;
    int t = threadIdx.x;
    int ty = t >> 3, tx = t & 7;

    float acc[4][6];
#pragma unroll
    for (int i = 0; i < 4; i++)
#pragma unroll
        for (int j = 0; j < 6; j++) acc[i][j] = 0.f;

    for (int kc = 0; kc < 512; kc += 32) {
        for (int f = t; f < 1024; f += 256) {
            int r = f >> 3, q = f & 7;
            float4 v = *reinterpret_cast<const float4*>(&g_h2[(size_t)(r0 + r) * DDIM + k0 + kc + q * 4]);
            As[q * 4 + 0][r] = v.x; As[q * 4 + 1][r] = v.y;
            As[q * 4 + 2][r] = v.z; As[q * 4 + 3][r] = v.w;
        }
        for (int f = t; f < 336; f += 256) {
            int c = f >> 3, q = f & 7;
            const float* wr = (c < 21) ? (w8c + (size_t)c * DDIM) : (w8d + (size_t)(c - 21) * DDIM);
            float4 v = *reinterpret_cast<const float4*>(wr + k0 + kc + q * 4);
            Bs[q * 4 + 0][c] = v.x; Bs[q * 4 + 1][c] = v.y;
            Bs[q * 4 + 2][c] = v.z; Bs[q * 4 + 3][c] = v.w;
        }
        __syncthreads();
#pragma unroll
        for (int kk = 0; kk < 32; kk++) {
            float a[4], b[6];
#pragma unroll
            for (int i = 0; i < 4; i++) a[i] = As[kk][ty * 4 + i];
#pragma unroll
            for (int j = 0; j < 6; j++) b[j] = Bs[kk][tx * 6 + j];
#pragma unroll
            for (int i = 0; i < 4; i++)
#pragma unroll
                for (int j = 0; j < 6; j++) acc[i][j] = fmaf(a[i], b[j], acc[i][j]);
        }
        __syncthreads();
    }
#pragma unroll
    for (int i = 0; i < 4; i++) {
        int r = r0 + ty * 4 + i;
#pragma unroll
        for (int j = 0; j < 6; j++) {
            g_hpart[(size_t)ks * R_ROIS * 48 + (size_t)r * 48 + tx * 6 + j] = acc[i][j];
        }
    }
}

__global__ __launch_bounds__(256) void heads_reduce(const float* __restrict__ b8c,
                                                    const float* __restrict__ b8d) {
    int i = blockIdx.x * 256 + threadIdx.x;
    if (i >= R_ROIS * 42) return;
    int r = i / 42, c = i - r * 42;
    float s = 0.f;
#pragma unroll
    for (int ks = 0; ks < 8; ks++) s += g_hpart[(size_t)ks * R_ROIS * 48 + (size_t)r * 48 + c];
    if (c < 21) g_xc[r * NCLS + c] = fmaxf(s + b8c[c], 0.f);
    else        g_xd[r * NCLS + (c - 21)] = fmaxf(s + b8d[c - 21], 0.f);
}

// ---------------------------------------------------------------------------
// Softmax epilogue
// ---------------------------------------------------------------------------
__global__ __launch_bounds__(256) void colstats_kernel() {
    __shared__ float red[256];
    int c = blockIdx.x;
    int t = threadIdx.x;
    float m = -INFINITY;
    for (int r = t; r < R_ROIS; r += 256) m = fmaxf(m, g_xd[r * NCLS + c]);
    red[t] = m;
    __syncthreads();
    for (int s = 128; s; s >>= 1) {
        if (t < s) red[t] = fmaxf(red[t], red[t + s]);
        __syncthreads();
    }
    float cm = red[0];
    __syncthreads();
    float s2 = 0.f;
    for (int r = t; r < R_ROIS; r += 256) s2 += expf(g_xd[r * NCLS + c] - cm);
    red[t] = s2;
    __syncthreads();
    for (int s = 128; s; s >>= 1) {
        if (t < s) red[t] += red[t + s];
        __syncthreads();
    }
    if (t == 0) { g_colmax[c] = cm; g_colsum[c] = red[0]; }
}

__global__ __launch_bounds__(256) void finalize_kernel(float* __restrict__ out) {
    int warp = threadIdx.x >> 5;
    int lane = threadIdx.x & 31;
    int r = blockIdx.x * 8 + warp;
    if (r >= R_ROIS) return;

    float v = (lane < NCLS) ? g_xc[r * NCLS + lane] : -INFINITY;
    float m = v;
#pragma unroll
    for (int off = 16; off; off >>= 1) m = fmaxf(m, __shfl_xor_sync(0xFFFFFFFFu, m, off));
    float e = (lane < NCLS) ? expf(v - m) : 0.f;
    float s = e;
#pragma unroll
    for (int off = 16; off; off >>= 1) s += __shfl_xor_sync(0xFFFFFFFFu, s, off);

    if (lane < NCLS) {
        float dr = e / s;
        float smd = expf(g_xd[r * NCLS + lane] - g_colmax[lane]) / g_colsum[lane];
        out[OUT_DM + r * NCLS + lane] = dr * smd;
        out[OUT_DR + r * NCLS + lane] = dr;
    }
}

__global__ __launch_bounds__(256) void score_kernel(const float* __restrict__ dm,
                                                    float* __restrict__ score) {
    __shared__ float red[256];
    int c = blockIdx.x;
    int t = threadIdx.x;
    float s = 0.f;
    for (int r = t; r < R_ROIS; r += 256) s += dm[r * NCLS + c];
    red[t] = s;
    __syncthreads();
    for (int st = 128; st; st >>= 1) {
        if (t < st) red[t] += red[t + st];
        __syncthreads();
    }
    if (t == 0) score[c] = red[0];
}

// ---------------------------------------------------------------------------
// Launch — FC6 is launch #4 (profiler capture slot)
// ---------------------------------------------------------------------------
extern "C" void kernel_launch(void* const* d_in, const int* in_sizes, int n_in,
                              void* d_out, int out_size) {
    const float* x   = (const float*)d_in[0];
    const float* w6  = (const float*)d_in[1];
    const float* b6  = (const float*)d_in[2];
    const float* w7  = (const float*)d_in[3];
    const float* b7  = (const float*)d_in[4];
    const float* w8c = (const float*)d_in[5];
    const float* b8c = (const float*)d_in[6];
    const float* w8d = (const float*)d_in[7];
    const float* b8d = (const float*)d_in[8];
    const int*   ssw = (const int*)d_in[9];
    float* out = (float*)d_out;

    __half *p_yh, *p_yl, *p_w6h, *p_w7h, *p_h1h, *p_h1l;
    float *p_h2;
    cudaGetSymbolAddress((void**)&p_yh, g_yh);
    cudaGetSymbolAddress((void**)&p_yl, g_yl);
    cudaGetSymbolAddress((void**)&p_w6h, g_w6h);
    cudaGetSymbolAddress((void**)&p_w7h, g_w7h);
    cudaGetSymbolAddress((void**)&p_h1h, g_h1h);
    cudaGetSymbolAddress((void**)&p_h1l, g_h1l);
    cudaGetSymbolAddress((void**)&p_h2, g_h2);

    cudaFuncSetAttribute(gemm_mma64, cudaFuncAttributeMaxDynamicSharedMemorySize, SMEM64);
    cudaFuncSetAttribute(gemm_mma128, cudaFuncAttributeMaxDynamicSharedMemorySize, SMEM128);
    cudaFuncSetAttribute(pool_kernel, cudaFuncAttributeMaxDynamicSharedMemorySize, POOL_SMEM);

    // 1) FC6 weight prep
    wsum_h_kernel<<<(DDIM * KHALF / 4 + 255) / 256, 256>>>(w6);

    // 2) fused SPP pool
    {
        dim3 grid(NORI, CCH / 32);
        pool_kernel<<<grid, 256, POOL_SMEM>>>(x);
    }

    // 3) SPP gather
    spp_gather_kernel<<<R_ROIS, 256>>>(ssw);

    // 4) FC6 (64x64, 3 CTA/SM), residual for half of K  [profiled]
    {
        dim3 grid(DDIM / 64, R_ROIS / 64);
        gemm_mma64<<<grid, 128, SMEM64>>>(p_yh, p_yl, p_w6h, b6, KHALF, 16,
                                          p_h1h, p_h1l);
    }

    // 5) FC7 weight prep
    w7_h_kernel<<<(DDIM * DDIM / 4 + 255) / 256, 256>>>(w7);

    // 6) FC7 (64x128, 2 CTA/SM), residual for half of K
    {
        dim3 grid(DDIM / 128, R_ROIS / 64);
        gemm_mma128<<<grid, 128, SMEM128>>>(p_h1h, p_h1l, p_w7h, b7, DDIM, 32, p_h2);
    }

    // 7) heads
    {
        dim3 grid(R_ROIS / 128, 8);
        heads_partial<<<grid, 256>>>(w8c, w8d);
        heads_reduce<<<(R_ROIS * 42 + 255) / 256, 256>>>(b8c, b8d);
    }

    // 8) softmax stats + finalize + score
    colstats_kernel<<<NCLS, 256>>>();
    finalize_kernel<<<R_ROIS / 8, 256>>>(out);
    score_kernel<<<NCLS, 256>>>(out + OUT_DM, out + OUT_SC);
}

// round 15
// speedup vs baseline: 1.1495x; 1.0556x over previous
#include <cuda_runtime.h>
#include <cuda_fp16.h>
#include <math.h>
#include <stdint.h>

// ---------------------------------------------------------------------------
// Problem constants
// ---------------------------------------------------------------------------
#define R_ROIS 2048
#define CCH    512
#define HWDIM  64
#define DDIM   4096
#define NCLS   21
#define KHALF  2048
#define NORI   58

#define OUT_DM 0
#define OUT_DR (R_ROIS * NCLS)
#define OUT_SC (2 * R_ROIS * NCLS)

// ---------------------------------------------------------------------------
// Scratch (device globals)
// ---------------------------------------------------------------------------
__device__ float g_vmax[NORI * NORI * CCH];
__device__ __half g_yh[R_ROIS * KHALF];
__device__ __half g_yl[R_ROIS * KHALF];
__device__ __half g_w6h[DDIM * KHALF];
__device__ __half g_w7h[DDIM * DDIM];
__device__ __half g_h1h[R_ROIS * DDIM];
__device__ __half g_h1l[R_ROIS * DDIM];
__device__ float g_h2[R_ROIS * DDIM];
__device__ float g_hpart[8 * R_ROIS * 48];
__device__ float g_xc[R_ROIS * NCLS];
__device__ float g_xd[R_ROIS * NCLS];
__device__ float g_colmax[NCLS];
__device__ float g_colsum[NCLS];

// ---------------------------------------------------------------------------
// Helpers
// ---------------------------------------------------------------------------
__device__ __forceinline__ uint32_t smem_u32(const void* p) {
    uint32_t a;
    asm("{ .reg .u64 t; cvta.to.shared.u64 t, %1; cvt.u32.u64 %0, t; }" : "=r"(a) : "l"(p));
    return a;
}

__device__ __forceinline__ void split2h(float v, __half& h, __half& l) {
    h = __float2half_rn(v);
    l = __float2half_rn(v - __half2float(h));
}

__device__ __forceinline__ uint32_t swz(int r, int g) {
    return (uint32_t)(r >> 3) * 1024u + (uint32_t)(r & 7) * 128u
         + (uint32_t)((g ^ (r & 7)) << 4);
}

#define CP_ASYNC16(dst, src) \
    asm volatile("cp.async.cg.shared.global [%0], [%1], 16;" :: "r"(dst), "l"(src))
#define CP_COMMIT() asm volatile("cp.async.commit_group;" ::: "memory")
#define CP_WAIT1()  asm volatile("cp.async.wait_group 1;" ::: "memory")

#define LDSM_X4(r0, r1, r2, r3, addr) \
    asm volatile("ldmatrix.sync.aligned.m8n8.x4.shared.b16 {%0,%1,%2,%3}, [%4];" \
                 : "=r"(r0), "=r"(r1), "=r"(r2), "=r"(r3) : "r"(addr))

#define MMA_F16(c, a0, a1, a2, a3, b0, b1) \
    asm volatile("mma.sync.aligned.m16n8k16.row.col.f32.f16.f16.f32 " \
                 "{%0,%1,%2,%3}, {%4,%5,%6,%7}, {%8,%9}, {%0,%1,%2,%3};" \
                 : "+f"((c)[0]), "+f"((c)[1]), "+f"((c)[2]), "+f"((c)[3]) \
                 : "r"(a0), "r"(a1), "r"(a2), "r"(a3), "r"(b0), "r"(b1))

// ---------------------------------------------------------------------------
// Fused SPP pool, row-staged: block = (4 yp outputs, 16 channels).
// raw rows staged in smem once (kills the 7x vertical global re-read).
// ---------------------------------------------------------------------------
#define PCH 16
#define PYP 4
#define POOL_SMEM ((PCH * 10 * 64 + PCH * 10 * 61) * 4)

__global__ __launch_bounds__(256) void pool_kernel(const float* __restrict__ x) {
    extern __shared__ float psm[];
    float* raw = psm;                        // [PCH][10][64]
    float* hm  = psm + PCH * 10 * 64;        // [PCH][10][61]
    int yp0 = blockIdx.x * PYP;
    int cg = blockIdx.y;
    int t = threadIdx.x;
    int nyp = (yp0 + PYP <= NORI) ? PYP : (NORI - yp0);
    int nrow = nyp + 6;

    // stage raw rows
    for (int idx = t; idx < PCH * nrow * 64; idx += 256) {
        int c = idx / (nrow * 64);
        int rem = idx - c * (nrow * 64);
        int row = rem >> 6;
        int xc = rem & 63;
        raw[(c * 10 + row) * 64 + xc] =
            x[((size_t)(cg * PCH + c) * HWDIM + (yp0 + row)) * HWDIM + xc];
    }
    __syncthreads();

    // horizontal 7-max from smem
    for (int idx = t; idx < PCH * nrow * NORI; idx += 256) {
        int c = idx / (nrow * NORI);
        int rem = idx - c * (nrow * NORI);
        int row = rem / NORI;
        int xp = rem - row * NORI;
        const float* rp = raw + (c * 10 + row) * 64 + xp;
        float m = rp[0];
#pragma unroll
        for (int d = 1; d < 7; d++) m = fmaxf(m, rp[d]);
        hm[(c * 10 + row) * 61 + xp] = m;
    }
    __syncthreads();

    // vertical 7-max, c-contiguous write
    for (int idx = t; idx < nyp * NORI * PCH; idx += 256) {
        int c = idx & (PCH - 1);
        int rest = idx >> 4;
        int xp = rest % NORI;
        int yl = rest / NORI;
        float m = hm[(c * 10 + yl) * 61 + xp];
#pragma unroll
        for (int y = 1; y < 7; y++) m = fmaxf(m, hm[(c * 10 + yl + y) * 61 + xp]);
        g_vmax[((size_t)(yp0 + yl) * NORI + xp) * CCH + cg * PCH + c] = m;
    }
}

// ---------------------------------------------------------------------------
// SPP gather: lv stored only for k < 1024 (FC6 residual never reads beyond)
// ---------------------------------------------------------------------------
__global__ __launch_bounds__(256) void spp_gather_kernel(const int* __restrict__ ssw) {
    __shared__ float ys[KHALF];
    int r = blockIdx.x;
    int y0 = ssw[r * 4 + 0];
    int x0 = ssw[r * 4 + 1];
    int t = threadIdx.x;
#pragma unroll
    for (int q = 0; q < 4; q++) {
        int i = q >> 1, j = q & 1;
        const float* src = g_vmax + ((size_t)(y0 + 7 * i) * NORI + (x0 + 7 * j)) * CCH;
        for (int c0 = 0; c0 < CCH; c0 += 256) {
            int c = c0 + t;
            ys[c * 4 + q] = src[c];
        }
    }
    __syncthreads();
    int k0 = t * 8;
    __half hv[8], lv[8];
#pragma unroll
    for (int u = 0; u < 8; u++) split2h(ys[k0 + u], hv[u], lv[u]);
    *reinterpret_cast<uint4*>(&g_yh[(size_t)r * KHALF + k0]) = *reinterpret_cast<uint4*>(hv);
    if (k0 < 1024)
        *reinterpret_cast<uint4*>(&g_yl[(size_t)r * KHALF + k0]) = *reinterpret_cast<uint4*>(lv);
}

// ---------------------------------------------------------------------------
// Weight fold + fp16 conversion
// ---------------------------------------------------------------------------
__global__ __launch_bounds__(256) void wsum_h_kernel(const float* __restrict__ w6) {
    int t = blockIdx.x * blockDim.x + threadIdx.x;
    const int NQ = DDIM * KHALF / 4;
    if (t >= NQ) return;
    int e = t / (KHALF / 4);
    int kq = t - e * (KHALF / 4);
    float4 av = reinterpret_cast<const float4*>(w6 + (size_t)e * DDIM)[kq];
    float4 bv = reinterpret_cast<const float4*>(w6 + (size_t)e * DDIM + KHALF)[kq];
    __half hv[4];
    hv[0] = __float2half_rn(av.x + bv.x);
    hv[1] = __float2half_rn(av.y + bv.y);
    hv[2] = __float2half_rn(av.z + bv.z);
    hv[3] = __float2half_rn(av.w + bv.w);
    *reinterpret_cast<uint2*>(&g_w6h[(size_t)e * KHALF + kq * 4]) = *reinterpret_cast<uint2*>(hv);
}

__global__ __launch_bounds__(256) void w7_h_kernel(const float* __restrict__ w7) {
    int t = blockIdx.x * blockDim.x + threadIdx.x;
    const int NQ = DDIM * DDIM / 4;
    if (t >= NQ) return;
    float4 v = reinterpret_cast<const float4*>(w7)[t];
    __half hv[4];
    hv[0] = __float2half_rn(v.x);
    hv[1] = __float2half_rn(v.y);
    hv[2] = __float2half_rn(v.z);
    hv[3] = __float2half_rn(v.w);
    *reinterpret_cast<uint2*>(&g_w7h[(size_t)t * 4]) = *reinterpret_cast<uint2*>(hv);
}

// ---------------------------------------------------------------------------
// GEMM variant A (FC6): CTA 64x64, 3 CTAs/SM, stage 24KB x3.
// Residual (Al) pass only for chunks kb < lo_nch. Cl stored only when
// bn0 < cl_cols (downstream residual coverage).
// ---------------------------------------------------------------------------
#define STG64 24576
#define SMEM64 (3 * STG64)

__device__ __forceinline__ void load_stage64(
    const __half* __restrict__ Ah, const __half* __restrict__ Al,
    const __half* __restrict__ Bh,
    int Kb, int bm0, int bn0, int k0, uint32_t sbase, int tid, bool load_al) {
#pragma unroll
    for (int it = 0; it < 12; it++) {
        int f = tid + it * 128;
        const __half* src;
        uint32_t dst;
        if (f < 512) {
            int r = f >> 3, g = f & 7;
            src = Ah + (size_t)(bm0 + r) * Kb + k0 + g * 8;
            dst = sbase + swz(r, g);
        } else if (f < 1024) {
            if (!load_al) continue;
            int fl = f - 512;
            int r = fl >> 3, g = fl & 7;
            src = Al + (size_t)(bm0 + r) * Kb + k0 + g * 8;
            dst = sbase + 8192u + swz(r, g);
        } else {
            int fl = f - 1024;
            int r = fl >> 3, g = fl & 7;
            src = Bh + (size_t)(bn0 + r) * Kb + k0 + g * 8;
            dst = sbase + 16384u + swz(r, g);
        }
        CP_ASYNC16(dst, src);
    }
}

__global__ __launch_bounds__(128, 3) void gemm_mma64(
    const __half* __restrict__ Ah, const __half* __restrict__ Al,
    const __half* __restrict__ Bh,
    const float* __restrict__ bias, int Kb, int lo_nch, int cl_cols,
    __half* __restrict__ Ch, __half* __restrict__ Cl) {
    extern __shared__ __align__(128) char smp[];
    uint32_t s0 = smem_u32(smp);

    int tid = threadIdx.x;
    int wid = tid >> 5;
    int lane = tid & 31;
    int wm = wid & 1;
    int wn = wid >> 1;
    int bm0 = blockIdx.y * 64;
    int bn0 = blockIdx.x * 64;

    int lr = lane & 7;
    int a_add8 = (lane >> 3) & 1;
    int a_gsel = lane >> 4;
    int b_add8 = lane >> 4;
    int b_gsel = (lane >> 3) & 1;

    uint32_t aoff[2], boff[2];
#pragma unroll
    for (int mf = 0; mf < 2; mf++)
        aoff[mf] = (uint32_t)(wm * 4 + mf * 2 + a_add8) * 1024u + (uint32_t)lr * 128u;
#pragma unroll
    for (int nf2 = 0; nf2 < 2; nf2++)
        boff[nf2] = (uint32_t)(wn * 4 + nf2 * 2 + b_add8) * 1024u + (uint32_t)lr * 128u;

    float acc[2][4][4];
#pragma unroll
    for (int i = 0; i < 2; i++)
#pragma unroll
        for (int j = 0; j < 4; j++)
#pragma unroll
            for (int q = 0; q < 4; q++) acc[i][j][q] = 0.f;

    int nch = Kb >> 6;

    load_stage64(Ah, Al, Bh, Kb, bm0, bn0, 0, s0, tid, 0 < lo_nch);
    CP_COMMIT();
    load_stage64(Ah, Al, Bh, Kb, bm0, bn0, 64, s0 + STG64, tid, 1 < lo_nch);
    CP_COMMIT();

    for (int kb = 0; kb < nch; kb++) {
        CP_WAIT1();
        __syncthreads();

        int nk = kb + 2;
        if (nk < nch) {
            load_stage64(Ah, Al, Bh, Kb, bm0, bn0, nk * 64,
                         s0 + (uint32_t)(nk % 3) * STG64, tid, nk < lo_nch);
        }
        CP_COMMIT();

        uint32_t abase = s0 + (uint32_t)(kb % 3) * STG64;
        uint32_t albase = abase + 8192u;
        uint32_t bbase = abase + 16384u;
        bool do_lo = (kb < lo_nch);

#pragma unroll
        for (int ks = 0; ks < 4; ks++) {
            uint32_t b[2][4];
#pragma unroll
            for (int nf2 = 0; nf2 < 2; nf2++) {
                uint32_t addr = bbase + boff[nf2] + (uint32_t)(((2 * ks + b_gsel) ^ lr) << 4);
                LDSM_X4(b[nf2][0], b[nf2][1], b[nf2][2], b[nf2][3], addr);
            }
            uint32_t a[2][4];
#pragma unroll
            for (int mf = 0; mf < 2; mf++) {
                uint32_t addr = abase + aoff[mf] + (uint32_t)(((2 * ks + a_gsel) ^ lr) << 4);
                LDSM_X4(a[mf][0], a[mf][1], a[mf][2], a[mf][3], addr);
            }
#pragma unroll
            for (int mf = 0; mf < 2; mf++)
#pragma unroll
                for (int nf = 0; nf < 4; nf++) {
                    uint32_t b0 = b[nf >> 1][(nf & 1) * 2];
                    uint32_t b1 = b[nf >> 1][(nf & 1) * 2 + 1];
                    MMA_F16(acc[mf][nf], a[mf][0], a[mf][1], a[mf][2], a[mf][3], b0, b1);
                }
            if (do_lo) {
#pragma unroll
                for (int mf = 0; mf < 2; mf++) {
                    uint32_t addr = albase + aoff[mf] + (uint32_t)(((2 * ks + a_gsel) ^ lr) << 4);
                    LDSM_X4(a[mf][0], a[mf][1], a[mf][2], a[mf][3], addr);
                }
#pragma unroll
                for (int mf = 0; mf < 2; mf++)
#pragma unroll
                    for (int nf = 0; nf < 4; nf++) {
                        uint32_t b0 = b[nf >> 1][(nf & 1) * 2];
                        uint32_t b1 = b[nf >> 1][(nf & 1) * 2 + 1];
                        MMA_F16(acc[mf][nf], a[mf][0], a[mf][1], a[mf][2], a[mf][3], b0, b1);
                    }
            }
        }
    }

    bool write_l = (bn0 < cl_cols);
    int gid = lane >> 2, tig = lane & 3;
#pragma unroll
    for (int mf = 0; mf < 2; mf++) {
#pragma unroll
        for (int nf = 0; nf < 4; nf++) {
            int row0 = bm0 + wm * 32 + mf * 16 + gid;
            int col = bn0 + wn * 32 + nf * 8 + tig * 2;
            float bx = __ldg(&bias[col]);
            float by = __ldg(&bias[col + 1]);
            float v00 = fmaxf(acc[mf][nf][0] + bx, 0.f);
            float v01 = fmaxf(acc[mf][nf][1] + by, 0.f);
            float v10 = fmaxf(acc[mf][nf][2] + bx, 0.f);
            float v11 = fmaxf(acc[mf][nf][3] + by, 0.f);
            __half h0, l0, h1, l1;
            split2h(v00, h0, l0); split2h(v01, h1, l1);
            *reinterpret_cast<__half2*>(&Ch[(size_t)row0 * DDIM + col]) = __halves2half2(h0, h1);
            if (write_l)
                *reinterpret_cast<__half2*>(&Cl[(size_t)row0 * DDIM + col]) = __halves2half2(l0, l1);
            split2h(v10, h0, l0); split2h(v11, h1, l1);
            *reinterpret_cast<__half2*>(&Ch[(size_t)(row0 + 8) * DDIM + col]) = __halves2half2(h0, h1);
            if (write_l)
                *reinterpret_cast<__half2*>(&Cl[(size_t)(row0 + 8) * DDIM + col]) = __halves2half2(l0, l1);
        }
    }
}

// ---------------------------------------------------------------------------
// GEMM variant B (FC7): CTA 64x128, 2 CTAs/SM, stage 32KB x3.
// Residual (Al) pass only for chunks kb < lo_nch.
// ---------------------------------------------------------------------------
#define STG128 32768
#define SMEM128 (3 * STG128)

__device__ __forceinline__ void load_stage128(
    const __half* __restrict__ Ah, const __half* __restrict__ Al,
    const __half* __restrict__ Bh,
    int Kb, int bm0, int bn0, int k0, uint32_t sbase, int tid, bool load_al) {
#pragma unroll
    for (int it = 0; it < 16; it++) {
        int f = tid + it * 128;
        const __half* src;
        uint32_t dst;
        if (f < 512) {
            int r = f >> 3, g = f & 7;
            src = Ah + (size_t)(bm0 + r) * Kb + k0 + g * 8;
            dst = sbase + swz(r, g);
        } else if (f < 1024) {
            if (!load_al) continue;
            int fl = f - 512;
            int r = fl >> 3, g = fl & 7;
            src = Al + (size_t)(bm0 + r) * Kb + k0 + g * 8;
            dst = sbase + 8192u + swz(r, g);
        } else {
            int fl = f - 1024;
            int r = fl >> 3, g = fl & 7;
            src = Bh + (size_t)(bn0 + r) * Kb + k0 + g * 8;
            dst = sbase + 16384u + swz(r, g);
        }
        CP_ASYNC16(dst, src);
    }
}

__global__ __launch_bounds__(128, 2) void gemm_mma128(
    const __half* __restrict__ Ah, const __half* __restrict__ Al,
    const __half* __restrict__ Bh,
    const float* __restrict__ bias, int Kb, int lo_nch,
    float* __restrict__ Cf) {
    extern __shared__ __align__(128) char smp[];
    uint32_t s0 = smem_u32(smp);

    int tid = threadIdx.x;
    int wid = tid >> 5;
    int lane = tid & 31;
    int wm = wid & 1;
    int wn = wid >> 1;
    int bm0 = blockIdx.y * 64;
    int bn0 = blockIdx.x * 128;

    int lr = lane & 7;
    int a_add8 = (lane >> 3) & 1;
    int a_gsel = lane >> 4;
    int b_add8 = lane >> 4;
    int b_gsel = (lane >> 3) & 1;

    uint32_t aoff[2], boff[4];
#pragma unroll
    for (int mf = 0; mf < 2; mf++)
        aoff[mf] = (uint32_t)(wm * 4 + mf * 2 + a_add8) * 1024u + (uint32_t)lr * 128u;
#pragma unroll
    for (int nf2 = 0; nf2 < 4; nf2++)
        boff[nf2] = (uint32_t)(wn * 8 + nf2 * 2 + b_add8) * 1024u + (uint32_t)lr * 128u;

    float acc[2][8][4];
#pragma unroll
    for (int i = 0; i < 2; i++)
#pragma unroll
        for (int j = 0; j < 8; j++)
#pragma unroll
            for (int q = 0; q < 4; q++) acc[i][j][q] = 0.f;

    int nch = Kb >> 6;

    load_stage128(Ah, Al, Bh, Kb, bm0, bn0, 0, s0, tid, 0 < lo_nch);
    CP_COMMIT();
    load_stage128(Ah, Al, Bh, Kb, bm0, bn0, 64, s0 + STG128, tid, 1 < lo_nch);
    CP_COMMIT();

    for (int kb = 0; kb < nch; kb++) {
        CP_WAIT1();
        __syncthreads();

        int nk = kb + 2;
        if (nk < nch) {
            load_stage128(Ah, Al, Bh, Kb, bm0, bn0, nk * 64,
                          s0 + (uint32_t)(nk % 3) * STG128, tid, nk < lo_nch);
        }
        CP_COMMIT();

        uint32_t abase = s0 + (uint32_t)(kb % 3) * STG128;
        uint32_t albase = abase + 8192u;
        uint32_t bbase = abase + 16384u;
        bool do_lo = (kb < lo_nch);

#pragma unroll
        for (int ks = 0; ks < 4; ks++) {
            uint32_t b[4][4];
#pragma unroll
            for (int nf2 = 0; nf2 < 4; nf2++) {
                uint32_t addr = bbase + boff[nf2] + (uint32_t)(((2 * ks + b_gsel) ^ lr) << 4);
                LDSM_X4(b[nf2][0], b[nf2][1], b[nf2][2], b[nf2][3], addr);
            }
            uint32_t a[2][4];
#pragma unroll
            for (int mf = 0; mf < 2; mf++) {
                uint32_t addr = abase + aoff[mf] + (uint32_t)(((2 * ks + a_gsel) ^ lr) << 4);
                LDSM_X4(a[mf][0], a[mf][1], a[mf][2], a[mf][3], addr);
            }
#pragma unroll
            for (int mf = 0; mf < 2; mf++)
#pragma unroll
                for (int nf = 0; nf < 8; nf++) {
                    uint32_t b0 = b[nf >> 1][(nf & 1) * 2];
                    uint32_t b1 = b[nf >> 1][(nf & 1) * 2 + 1];
                    MMA_F16(acc[mf][nf], a[mf][0], a[mf][1], a[mf][2], a[mf][3], b0, b1);
                }
            if (do_lo) {
#pragma unroll
                for (int mf = 0; mf < 2; mf++) {
                    uint32_t addr = albase + aoff[mf] + (uint32_t)(((2 * ks + a_gsel) ^ lr) << 4);
                    LDSM_X4(a[mf][0], a[mf][1], a[mf][2], a[mf][3], addr);
                }
#pragma unroll
                for (int mf = 0; mf < 2; mf++)
#pragma unroll
                    for (int nf = 0; nf < 8; nf++) {
                        uint32_t b0 = b[nf >> 1][(nf & 1) * 2];
                        uint32_t b1 = b[nf >> 1][(nf & 1) * 2 + 1];
                        MMA_F16(acc[mf][nf], a[mf][0], a[mf][1], a[mf][2], a[mf][3], b0, b1);
                    }
            }
        }
    }

    int gid = lane >> 2, tig = lane & 3;
#pragma unroll
    for (int mf = 0; mf < 2; mf++) {
#pragma unroll
        for (int nf = 0; nf < 8; nf++) {
            int row0 = bm0 + wm * 32 + mf * 16 + gid;
            int col = bn0 + wn * 64 + nf * 8 + tig * 2;
            float bx = __ldg(&bias[col]);
            float by = __ldg(&bias[col + 1]);
            float v00 = fmaxf(acc[mf][nf][0] + bx, 0.f);
            float v01 = fmaxf(acc[mf][nf][1] + by, 0.f);
            float v10 = fmaxf(acc[mf][nf][2] + bx, 0.f);
            float v11 = fmaxf(acc[mf][nf][3] + by, 0.f);
            *reinterpret_cast<float2*>(&Cf[(size_t)row0 * DDIM + col]) = make_float2(v00, v01);
            *reinterpret_cast<float2*>(&Cf[(size_t)(row0 + 8) * DDIM + col]) = make_float2(v10, v11);
        }
    }
}

// ---------------------------------------------------------------------------
// Heads split-K GEMM
// ---------------------------------------------------------------------------
__global__ __launch_bounds__(256) void heads_partial(const float* __restrict__ w8c,
                                                     const float* __restrict__ w8d) {
    __shared__ float As[32][132];
    __shared__ float Bs[32][48];
    int r0 = blockIdx.x * 128;
    int ks = blockIdx.y;
    int k0 = ks * 512;
    int t = threadIdx.x;
    int ty = t >> 3, tx = t & 7;

    float acc[4][6];
#pragma unroll
    for (int i = 0; i < 4; i++)
#pragma unroll
        for (int j = 0; j < 6; j++) acc[i][j] = 0.f;

    for (int kc = 0; kc < 512; kc += 32) {
        for (int f = t; f < 1024; f += 256) {
            int r = f >> 3, q = f & 7;
            float4 v = *reinterpret_cast<const float4*>(&g_h2[(size_t)(r0 + r) * DDIM + k0 + kc + q * 4]);
            As[q * 4 + 0][r] = v.x; As[q * 4 + 1][r] = v.y;
            As[q * 4 + 2][r] = v.z; As[q * 4 + 3][r] = v.w;
        }
        for (int f = t; f < 336; f += 256) {
            int c = f >> 3, q = f & 7;
            const float* wr = (c < 21) ? (w8c + (size_t)c * DDIM) : (w8d + (size_t)(c - 21) * DDIM);
            float4 v = *reinterpret_cast<const float4*>(wr + k0 + kc + q * 4);
            Bs[q * 4 + 0][c] = v.x; Bs[q * 4 + 1][c] = v.y;
            Bs[q * 4 + 2][c] = v.z; Bs[q * 4 + 3][c] = v.w;
        }
        __syncthreads();
#pragma unroll
        for (int kk = 0; kk < 32; kk++) {
            float a[4], b[6];
#pragma unroll
            for (int i = 0; i < 4; i++) a[i] = As[kk][ty * 4 + i];
#pragma unroll
            for (int j = 0; j < 6; j++) b[j] = Bs[kk][tx * 6 + j];
#pragma unroll
            for (int i = 0; i < 4; i++)
#pragma unroll
                for (int j = 0; j < 6; j++) acc[i][j] = fmaf(a[i], b[j], acc[i][j]);
        }
        __syncthreads();
    }
#pragma unroll
    for (int i = 0; i < 4; i++) {
        int r = r0 + ty * 4 + i;
#pragma unroll
        for (int j = 0; j < 6; j++) {
            g_hpart[(size_t)ks * R_ROIS * 48 + (size_t)r * 48 + tx * 6 + j] = acc[i][j];
        }
    }
}

__global__ __launch_bounds__(256) void heads_reduce(const float* __restrict__ b8c,
                                                    const float* __restrict__ b8d) {
    int i = blockIdx.x * 256 + threadIdx.x;
    if (i >= R_ROIS * 42) return;
    int r = i / 42, c = i - r * 42;
    float s = 0.f;
#pragma unroll
    for (int ks = 0; ks < 8; ks++) s += g_hpart[(size_t)ks * R_ROIS * 48 + (size_t)r * 48 + c];
    if (c < 21) g_xc[r * NCLS + c] = fmaxf(s + b8c[c], 0.f);
    else        g_xd[r * NCLS + (c - 21)] = fmaxf(s + b8d[c - 21], 0.f);
}

// ---------------------------------------------------------------------------
// Softmax epilogue
// ---------------------------------------------------------------------------
__global__ __launch_bounds__(256) void colstats_kernel() {
    __shared__ float red[256];
    int c = blockIdx.x;
    int t = threadIdx.x;
    float m = -INFINITY;
    for (int r = t; r < R_ROIS; r += 256) m = fmaxf(m, g_xd[r * NCLS + c]);
    red[t] = m;
    __syncthreads();
    for (int s = 128; s; s >>= 1) {
        if (t < s) red[t] = fmaxf(red[t], red[t + s]);
        __syncthreads();
    }
    float cm = red[0];
    __syncthreads();
    float s2 = 0.f;
    for (int r = t; r < R_ROIS; r += 256) s2 += expf(g_xd[r * NCLS + c] - cm);
    red[t] = s2;
    __syncthreads();
    for (int s = 128; s; s >>= 1) {
        if (t < s) red[t] += red[t + s];
        __syncthreads();
    }
    if (t == 0) { g_colmax[c] = cm; g_colsum[c] = red[0]; }
}

__global__ __launch_bounds__(256) void finalize_kernel(float* __restrict__ out) {
    int warp = threadIdx.x >> 5;
    int lane = threadIdx.x & 31;
    int r = blockIdx.x * 8 + warp;
    if (r >= R_ROIS) return;

    float v = (lane < NCLS) ? g_xc[r * NCLS + lane] : -INFINITY;
    float m = v;
#pragma unroll
    for (int off = 16; off; off >>= 1) m = fmaxf(m, __shfl_xor_sync(0xFFFFFFFFu, m, off));
    float e = (lane < NCLS) ? expf(v - m) : 0.f;
    float s = e;
#pragma unroll
    for (int off = 16; off; off >>= 1) s += __shfl_xor_sync(0xFFFFFFFFu, s, off);

    if (lane < NCLS) {
        float dr = e / s;
        float smd = expf(g_xd[r * NCLS + lane] - g_colmax[lane]) / g_colsum[lane];
        out[OUT_DM + r * NCLS + lane] = dr * smd;
        out[OUT_DR + r * NCLS + lane] = dr;
    }
}

__global__ __launch_bounds__(256) void score_kernel(const float* __restrict__ dm,
                                                    float* __restrict__ score) {
    __shared__ float red[256];
    int c = blockIdx.x;
    int t = threadIdx.x;
    float s = 0.f;
    for (int r = t; r < R_ROIS; r += 256) s += dm[r * NCLS + c];
    red[t] = s;
    __syncthreads();
    for (int st = 128; st; st >>= 1) {
        if (t < st) red[t] += red[t + st];
        __syncthreads();
    }
    if (t == 0) score[c] = red[0];
}

// ---------------------------------------------------------------------------
// Launch — FC6 is launch #4 (profiler capture slot)
// ---------------------------------------------------------------------------
extern "C" void kernel_launch(void* const* d_in, const int* in_sizes, int n_in,
                              void* d_out, int out_size) {
    const float* x   = (const float*)d_in[0];
    const float* w6  = (const float*)d_in[1];
    const float* b6  = (const float*)d_in[2];
    const float* w7  = (const float*)d_in[3];
    const float* b7  = (const float*)d_in[4];
    const float* w8c = (const float*)d_in[5];
    const float* b8c = (const float*)d_in[6];
    const float* w8d = (const float*)d_in[7];
    const float* b8d = (const float*)d_in[8];
    const int*   ssw = (const int*)d_in[9];
    float* out = (float*)d_out;

    __half *p_yh, *p_yl, *p_w6h, *p_w7h, *p_h1h, *p_h1l;
    float *p_h2;
    cudaGetSymbolAddress((void**)&p_yh, g_yh);
    cudaGetSymbolAddress((void**)&p_yl, g_yl);
    cudaGetSymbolAddress((void**)&p_w6h, g_w6h);
    cudaGetSymbolAddress((void**)&p_w7h, g_w7h);
    cudaGetSymbolAddress((void**)&p_h1h, g_h1h);
    cudaGetSymbolAddress((void**)&p_h1l, g_h1l);
    cudaGetSymbolAddress((void**)&p_h2, g_h2);

    cudaFuncSetAttribute(gemm_mma64, cudaFuncAttributeMaxDynamicSharedMemorySize, SMEM64);
    cudaFuncSetAttribute(gemm_mma128, cudaFuncAttributeMaxDynamicSharedMemorySize, SMEM128);
    cudaFuncSetAttribute(pool_kernel, cudaFuncAttributeMaxDynamicSharedMemorySize, POOL_SMEM);

    // 1) FC6 weight prep
    wsum_h_kernel<<<(DDIM * KHALF / 4 + 255) / 256, 256>>>(w6);

    // 2) fused SPP pool (row-staged)
    {
        dim3 grid((NORI + PYP - 1) / PYP, CCH / PCH);
        pool_kernel<<<grid, 256, POOL_SMEM>>>(x);
    }

    // 3) SPP gather
    spp_gather_kernel<<<R_ROIS, 256>>>(ssw);

    // 4) FC6 (64x64, 3 CTA/SM), residual for half of K  [profiled]
    {
        dim3 grid(DDIM / 64, R_ROIS / 64);
        gemm_mma64<<<grid, 128, SMEM64>>>(p_yh, p_yl, p_w6h, b6, KHALF, 16, 2048,
                                          p_h1h, p_h1l);
    }

    // 5) FC7 weight prep
    w7_h_kernel<<<(DDIM * DDIM / 4 + 255) / 256, 256>>>(w7);

    // 6) FC7 (64x128, 2 CTA/SM), residual for half of K
    {
        dim3 grid(DDIM / 128, R_ROIS / 64);
        gemm_mma128<<<grid, 128, SMEM128>>>(p_h1h, p_h1l, p_w7h, b7, DDIM, 32, p_h2);
    }

    // 7) heads
    {
        dim3 grid(R_ROIS / 128, 8);
        heads_partial<<<grid, 256>>>(w8c, w8d);
        heads_reduce<<<(R_ROIS * 42 + 255) / 256, 256>>>(b8c, b8d);
    }

    // 8) softmax stats + finalize + score
    colstats_kernel<<<NCLS, 256>>>();
    finalize_kernel<<<R_ROIS / 8, 256>>>(out);
    score_kernel<<<NCLS, 256>>>(out + OUT_DM, out + OUT_SC);
}

// round 16
// speedup vs baseline: 1.2538x; 1.0908x over previous
#include <cuda_runtime.h>
#include <cuda_fp16.h>
#include <math.h>
#include <stdint.h>

// ---------------------------------------------------------------------------
// Problem constants
// ---------------------------------------------------------------------------
#define R_ROIS 2048
#define CCH    512
#define HWDIM  64
#define DDIM   4096
#define NCLS   21
#define KHALF  2048
#define NORI   58

#define OUT_DM 0
#define OUT_DR (R_ROIS * NCLS)
#define OUT_SC (2 * R_ROIS * NCLS)

// ---------------------------------------------------------------------------
// Scratch (device globals)
// ---------------------------------------------------------------------------
__device__ float g_vmax[NORI * NORI * CCH];
__device__ __half g_yh[R_ROIS * KHALF];
__device__ __half g_yl[R_ROIS * KHALF];
__device__ __half g_w6h[DDIM * KHALF];
__device__ __half g_w7h[DDIM * DDIM];
__device__ __half g_h1h[R_ROIS * DDIM];
__device__ __half g_h1l[R_ROIS * DDIM];
__device__ float g_h2[R_ROIS * DDIM];
__device__ float g_hpart[8 * R_ROIS * 48];
__device__ float g_xc[R_ROIS * NCLS];
__device__ float g_xd[R_ROIS * NCLS];
__device__ float g_colmax[NCLS];
__device__ float g_colsum[NCLS];

// ---------------------------------------------------------------------------
// Helpers
// ---------------------------------------------------------------------------
__device__ __forceinline__ uint32_t smem_u32(const void* p) {
    uint32_t a;
    asm("{ .reg .u64 t; cvta.to.shared.u64 t, %1; cvt.u32.u64 %0, t; }" : "=r"(a) : "l"(p));
    return a;
}

__device__ __forceinline__ void split2h(float v, __half& h, __half& l) {
    h = __float2half_rn(v);
    l = __float2half_rn(v - __half2float(h));
}

__device__ __forceinline__ uint32_t swz(int r, int g) {
    return (uint32_t)(r >> 3) * 1024u + (uint32_t)(r & 7) * 128u
         + (uint32_t)((g ^ (r & 7)) << 4);
}

#define CP_ASYNC16(dst, src) \
    asm volatile("cp.async.cg.shared.global [%0], [%1], 16;" :: "r"(dst), "l"(src))
#define CP_COMMIT() asm volatile("cp.async.commit_group;" ::: "memory")
#define CP_WAIT1()  asm volatile("cp.async.wait_group 1;" ::: "memory")

#define LDSM_X4(r0, r1, r2, r3, addr) \
    asm volatile("ldmatrix.sync.aligned.m8n8.x4.shared.b16 {%0,%1,%2,%3}, [%4];" \
                 : "=r"(r0), "=r"(r1), "=r"(r2), "=r"(r3) : "r"(addr))

#define MMA_F16(c, a0, a1, a2, a3, b0, b1) \
    asm volatile("mma.sync.aligned.m16n8k16.row.col.f32.f16.f16.f32 " \
                 "{%0,%1,%2,%3}, {%4,%5,%6,%7}, {%8,%9}, {%0,%1,%2,%3};" \
                 : "+f"((c)[0]), "+f"((c)[1]), "+f"((c)[2]), "+f"((c)[3]) \
                 : "r"(a0), "r"(a1), "r"(a2), "r"(a3), "r"(b0), "r"(b1))

// ---------------------------------------------------------------------------
// Fused SPP pool, row-staged
// ---------------------------------------------------------------------------
#define PCH 16
#define PYP 4
#define POOL_SMEM ((PCH * 10 * 64 + PCH * 10 * 61) * 4)

__global__ __launch_bounds__(256) void pool_kernel(const float* __restrict__ x) {
    extern __shared__ float psm[];
    float* raw = psm;                        // [PCH][10][64]
    float* hm  = psm + PCH * 10 * 64;        // [PCH][10][61]
    int yp0 = blockIdx.x * PYP;
    int cg = blockIdx.y;
    int t = threadIdx.x;
    int nyp = (yp0 + PYP <= NORI) ? PYP : (NORI - yp0);
    int nrow = nyp + 6;

    for (int idx = t; idx < PCH * nrow * 64; idx += 256) {
        int c = idx / (nrow * 64);
        int rem = idx - c * (nrow * 64);
        int row = rem >> 6;
        int xc = rem & 63;
        raw[(c * 10 + row) * 64 + xc] =
            x[((size_t)(cg * PCH + c) * HWDIM + (yp0 + row)) * HWDIM + xc];
    }
    __syncthreads();

    for (int idx = t; idx < PCH * nrow * NORI; idx += 256) {
        int c = idx / (nrow * NORI);
        int rem = idx - c * (nrow * NORI);
        int row = rem / NORI;
        int xp = rem - row * NORI;
        const float* rp = raw + (c * 10 + row) * 64 + xp;
        float m = rp[0];
#pragma unroll
        for (int d = 1; d < 7; d++) m = fmaxf(m, rp[d]);
        hm[(c * 10 + row) * 61 + xp] = m;
    }
    __syncthreads();

    for (int idx = t; idx < nyp * NORI * PCH; idx += 256) {
        int c = idx & (PCH - 1);
        int rest = idx >> 4;
        int xp = rest % NORI;
        int yl = rest / NORI;
        float m = hm[(c * 10 + yl) * 61 + xp];
#pragma unroll
        for (int y = 1; y < 7; y++) m = fmaxf(m, hm[(c * 10 + yl + y) * 61 + xp]);
        g_vmax[((size_t)(yp0 + yl) * NORI + xp) * CCH + cg * PCH + c] = m;
    }
}

// ---------------------------------------------------------------------------
// SPP gather: lv stored only for k < 512 (FC6 residual covers k < 512)
// ---------------------------------------------------------------------------
__global__ __launch_bounds__(256) void spp_gather_kernel(const int* __restrict__ ssw) {
    __shared__ float ys[KHALF];
    int r = blockIdx.x;
    int y0 = ssw[r * 4 + 0];
    int x0 = ssw[r * 4 + 1];
    int t = threadIdx.x;
#pragma unroll
    for (int q = 0; q < 4; q++) {
        int i = q >> 1, j = q & 1;
        const float* src = g_vmax + ((size_t)(y0 + 7 * i) * NORI + (x0 + 7 * j)) * CCH;
        for (int c0 = 0; c0 < CCH; c0 += 256) {
            int c = c0 + t;
            ys[c * 4 + q] = src[c];
        }
    }
    __syncthreads();
    int k0 = t * 8;
    __half hv[8], lv[8];
#pragma unroll
    for (int u = 0; u < 8; u++) split2h(ys[k0 + u], hv[u], lv[u]);
    *reinterpret_cast<uint4*>(&g_yh[(size_t)r * KHALF + k0]) = *reinterpret_cast<uint4*>(hv);
    if (k0 < 512)
        *reinterpret_cast<uint4*>(&g_yl[(size_t)r * KHALF + k0]) = *reinterpret_cast<uint4*>(lv);
}

// ---------------------------------------------------------------------------
// Weight fold + fp16 conversion
// ---------------------------------------------------------------------------
__global__ __launch_bounds__(256) void wsum_h_kernel(const float* __restrict__ w6) {
    int t = blockIdx.x * blockDim.x + threadIdx.x;
    const int NQ = DDIM * KHALF / 4;
    if (t >= NQ) return;
    int e = t / (KHALF / 4);
    int kq = t - e * (KHALF / 4);
    float4 av = reinterpret_cast<const float4*>(w6 + (size_t)e * DDIM)[kq];
    float4 bv = reinterpret_cast<const float4*>(w6 + (size_t)e * DDIM + KHALF)[kq];
    __half hv[4];
    hv[0] = __float2half_rn(av.x + bv.x);
    hv[1] = __float2half_rn(av.y + bv.y);
    hv[2] = __float2half_rn(av.z + bv.z);
    hv[3] = __float2half_rn(av.w + bv.w);
    *reinterpret_cast<uint2*>(&g_w6h[(size_t)e * KHALF + kq * 4]) = *reinterpret_cast<uint2*>(hv);
}

__global__ __launch_bounds__(256) void w7_h_kernel(const float* __restrict__ w7) {
    int t = blockIdx.x * blockDim.x + threadIdx.x;
    const int NQ = DDIM * DDIM / 4;
    if (t >= NQ) return;
    float4 v = reinterpret_cast<const float4*>(w7)[t];
    __half hv[4];
    hv[0] = __float2half_rn(v.x);
    hv[1] = __float2half_rn(v.y);
    hv[2] = __float2half_rn(v.z);
    hv[3] = __float2half_rn(v.w);
    *reinterpret_cast<uint2*>(&g_w7h[(size_t)t * 4]) = *reinterpret_cast<uint2*>(hv);
}

// ---------------------------------------------------------------------------
// GEMM variant A (FC6): CTA 64x64, 3 CTAs/SM, stage 24KB x3.
// Residual (Al) pass only for chunks kb < lo_nch; Cl stored when bn0 < cl_cols.
// ---------------------------------------------------------------------------
#define STG64 24576
#define SMEM64 (3 * STG64)

__device__ __forceinline__ void load_stage64(
    const __half* __restrict__ Ah, const __half* __restrict__ Al,
    const __half* __restrict__ Bh,
    int Kb, int bm0, int bn0, int k0, uint32_t sbase, int tid, bool load_al) {
#pragma unroll
    for (int it = 0; it < 12; it++) {
        int f = tid + it * 128;
        const __half* src;
        uint32_t dst;
        if (f < 512) {
            int r = f >> 3, g = f & 7;
            src = Ah + (size_t)(bm0 + r) * Kb + k0 + g * 8;
            dst = sbase + swz(r, g);
        } else if (f < 1024) {
            if (!load_al) continue;
            int fl = f - 512;
            int r = fl >> 3, g = fl & 7;
            src = Al + (size_t)(bm0 + r) * Kb + k0 + g * 8;
            dst = sbase + 8192u + swz(r, g);
        } else {
            int fl = f - 1024;
            int r = fl >> 3, g = fl & 7;
            src = Bh + (size_t)(bn0 + r) * Kb + k0 + g * 8;
            dst = sbase + 16384u + swz(r, g);
        }
        CP_ASYNC16(dst, src);
    }
}

__global__ __launch_bounds__(128, 3) void gemm_mma64(
    const __half* __restrict__ Ah, const __half* __restrict__ Al,
    const __half* __restrict__ Bh,
    const float* __restrict__ bias, int Kb, int lo_nch, int cl_cols,
    __half* __restrict__ Ch, __half* __restrict__ Cl) {
    extern __shared__ __align__(128) char smp[];
    uint32_t s0 = smem_u32(smp);

    int tid = threadIdx.x;
    int wid = tid >> 5;
    int lane = tid & 31;
    int wm = wid & 1;
    int wn = wid >> 1;
    int bm0 = blockIdx.y * 64;
    int bn0 = blockIdx.x * 64;

    int lr = lane & 7;
    int a_add8 = (lane >> 3) & 1;
    int a_gsel = lane >> 4;
    int b_add8 = lane >> 4;
    int b_gsel = (lane >> 3) & 1;

    uint32_t aoff[2], boff[2];
#pragma unroll
    for (int mf = 0; mf < 2; mf++)
        aoff[mf] = (uint32_t)(wm * 4 + mf * 2 + a_add8) * 1024u + (uint32_t)lr * 128u;
#pragma unroll
    for (int nf2 = 0; nf2 < 2; nf2++)
        boff[nf2] = (uint32_t)(wn * 4 + nf2 * 2 + b_add8) * 1024u + (uint32_t)lr * 128u;

    float acc[2][4][4];
#pragma unroll
    for (int i = 0; i < 2; i++)
#pragma unroll
        for (int j = 0; j < 4; j++)
#pragma unroll
            for (int q = 0; q < 4; q++) acc[i][j][q] = 0.f;

    int nch = Kb >> 6;

    load_stage64(Ah, Al, Bh, Kb, bm0, bn0, 0, s0, tid, 0 < lo_nch);
    CP_COMMIT();
    load_stage64(Ah, Al, Bh, Kb, bm0, bn0, 64, s0 + STG64, tid, 1 < lo_nch);
    CP_COMMIT();

    for (int kb = 0; kb < nch; kb++) {
        CP_WAIT1();
        __syncthreads();

        int nk = kb + 2;
        if (nk < nch) {
            load_stage64(Ah, Al, Bh, Kb, bm0, bn0, nk * 64,
                         s0 + (uint32_t)(nk % 3) * STG64, tid, nk < lo_nch);
        }
        CP_COMMIT();

        uint32_t abase = s0 + (uint32_t)(kb % 3) * STG64;
        uint32_t albase = abase + 8192u;
        uint32_t bbase = abase + 16384u;
        bool do_lo = (kb < lo_nch);

#pragma unroll
        for (int ks = 0; ks < 4; ks++) {
            uint32_t b[2][4];
#pragma unroll
            for (int nf2 = 0; nf2 < 2; nf2++) {
                uint32_t addr = bbase + boff[nf2] + (uint32_t)(((2 * ks + b_gsel) ^ lr) << 4);
                LDSM_X4(b[nf2][0], b[nf2][1], b[nf2][2], b[nf2][3], addr);
            }
            uint32_t a[2][4];
#pragma unroll
            for (int mf = 0; mf < 2; mf++) {
                uint32_t addr = abase + aoff[mf] + (uint32_t)(((2 * ks + a_gsel) ^ lr) << 4);
                LDSM_X4(a[mf][0], a[mf][1], a[mf][2], a[mf][3], addr);
            }
#pragma unroll
            for (int mf = 0; mf < 2; mf++)
#pragma unroll
                for (int nf = 0; nf < 4; nf++) {
                    uint32_t b0 = b[nf >> 1][(nf & 1) * 2];
                    uint32_t b1 = b[nf >> 1][(nf & 1) * 2 + 1];
                    MMA_F16(acc[mf][nf], a[mf][0], a[mf][1], a[mf][2], a[mf][3], b0, b1);
                }
            if (do_lo) {
#pragma unroll
                for (int mf = 0; mf < 2; mf++) {
                    uint32_t addr = albase + aoff[mf] + (uint32_t)(((2 * ks + a_gsel) ^ lr) << 4);
                    LDSM_X4(a[mf][0], a[mf][1], a[mf][2], a[mf][3], addr);
                }
#pragma unroll
                for (int mf = 0; mf < 2; mf++)
#pragma unroll
                    for (int nf = 0; nf < 4; nf++) {
                        uint32_t b0 = b[nf >> 1][(nf & 1) * 2];
                        uint32_t b1 = b[nf >> 1][(nf & 1) * 2 + 1];
                        MMA_F16(acc[mf][nf], a[mf][0], a[mf][1], a[mf][2], a[mf][3], b0, b1);
                    }
            }
        }
    }

    bool write_l = (bn0 < cl_cols);
    int gid = lane >> 2, tig = lane & 3;
#pragma unroll
    for (int mf = 0; mf < 2; mf++) {
#pragma unroll
        for (int nf = 0; nf < 4; nf++) {
            int row0 = bm0 + wm * 32 + mf * 16 + gid;
            int col = bn0 + wn * 32 + nf * 8 + tig * 2;
            float bx = __ldg(&bias[col]);
            float by = __ldg(&bias[col + 1]);
            float v00 = fmaxf(acc[mf][nf][0] + bx, 0.f);
            float v01 = fmaxf(acc[mf][nf][1] + by, 0.f);
            float v10 = fmaxf(acc[mf][nf][2] + bx, 0.f);
            float v11 = fmaxf(acc[mf][nf][3] + by, 0.f);
            __half h0, l0, h1, l1;
            split2h(v00, h0, l0); split2h(v01, h1, l1);
            *reinterpret_cast<__half2*>(&Ch[(size_t)row0 * DDIM + col]) = __halves2half2(h0, h1);
            if (write_l)
                *reinterpret_cast<__half2*>(&Cl[(size_t)row0 * DDIM + col]) = __halves2half2(l0, l1);
            split2h(v10, h0, l0); split2h(v11, h1, l1);
            *reinterpret_cast<__half2*>(&Ch[(size_t)(row0 + 8) * DDIM + col]) = __halves2half2(h0, h1);
            if (write_l)
                *reinterpret_cast<__half2*>(&Cl[(size_t)(row0 + 8) * DDIM + col]) = __halves2half2(l0, l1);
        }
    }
}

// ---------------------------------------------------------------------------
// GEMM variant B (FC7): CTA 64x128, 2 CTAs/SM, stage 32KB x3.
// Residual (Al) pass only for chunks kb < lo_nch.
// ---------------------------------------------------------------------------
#define STG128 32768
#define SMEM128 (3 * STG128)

__device__ __forceinline__ void load_stage128(
    const __half* __restrict__ Ah, const __half* __restrict__ Al,
    const __half* __restrict__ Bh,
    int Kb, int bm0, int bn0, int k0, uint32_t sbase, int tid, bool load_al) {
#pragma unroll
    for (int it = 0; it < 16; it++) {
        int f = tid + it * 128;
        const __half* src;
        uint32_t dst;
        if (f < 512) {
            int r = f >> 3, g = f & 7;
            src = Ah + (size_t)(bm0 + r) * Kb + k0 + g * 8;
            dst = sbase + swz(r, g);
        } else if (f < 1024) {
            if (!load_al) continue;
            int fl = f - 512;
            int r = fl >> 3, g = fl & 7;
            src = Al + (size_t)(bm0 + r) * Kb + k0 + g * 8;
            dst = sbase + 8192u + swz(r, g);
        } else {
            int fl = f - 1024;
            int r = fl >> 3, g = fl & 7;
            src = Bh + (size_t)(bn0 + r) * Kb + k0 + g * 8;
            dst = sbase + 16384u + swz(r, g);
        }
        CP_ASYNC16(dst, src);
    }
}

__global__ __launch_bounds__(128, 2) void gemm_mma128(
    const __half* __restrict__ Ah, const __half* __restrict__ Al,
    const __half* __restrict__ Bh,
    const float* __restrict__ bias, int Kb, int lo_nch,
    float* __restrict__ Cf) {
    extern __shared__ __align__(128) char smp[];
    uint32_t s0 = smem_u32(smp);

    int tid = threadIdx.x;
    int wid = tid >> 5;
    int lane = tid & 31;
    int wm = wid & 1;
    int wn = wid >> 1;
    int bm0 = blockIdx.y * 64;
    int bn0 = blockIdx.x * 128;

    int lr = lane & 7;
    int a_add8 = (lane >> 3) & 1;
    int a_gsel = lane >> 4;
    int b_add8 = lane >> 4;
    int b_gsel = (lane >> 3) & 1;

    uint32_t aoff[2], boff[4];
#pragma unroll
    for (int mf = 0; mf < 2; mf++)
        aoff[mf] = (uint32_t)(wm * 4 + mf * 2 + a_add8) * 1024u + (uint32_t)lr * 128u;
#pragma unroll
    for (int nf2 = 0; nf2 < 4; nf2++)
        boff[nf2] = (uint32_t)(wn * 8 + nf2 * 2 + b_add8) * 1024u + (uint32_t)lr * 128u;

    float acc[2][8][4];
#pragma unroll
    for (int i = 0; i < 2; i++)
#pragma unroll
        for (int j = 0; j < 8; j++)
#pragma unroll
            for (int q = 0; q < 4; q++) acc[i][j][q] = 0.f;

    int nch = Kb >> 6;

    load_stage128(Ah, Al, Bh, Kb, bm0, bn0, 0, s0, tid, 0 < lo_nch);
    CP_COMMIT();
    load_stage128(Ah, Al, Bh, Kb, bm0, bn0, 64, s0 + STG128, tid, 1 < lo_nch);
    CP_COMMIT();

    for (int kb = 0; kb < nch; kb++) {
        CP_WAIT1();
        __syncthreads();

        int nk = kb + 2;
        if (nk < nch) {
            load_stage128(Ah, Al, Bh, Kb, bm0, bn0, nk * 64,
                          s0 + (uint32_t)(nk % 3) * STG128, tid, nk < lo_nch);
        }
        CP_COMMIT();

        uint32_t abase = s0 + (uint32_t)(kb % 3) * STG128;
        uint32_t albase = abase + 8192u;
        uint32_t bbase = abase + 16384u;
        bool do_lo = (kb < lo_nch);

#pragma unroll
        for (int ks = 0; ks < 4; ks++) {
            uint32_t b[4][4];
#pragma unroll
            for (int nf2 = 0; nf2 < 4; nf2++) {
                uint32_t addr = bbase + boff[nf2] + (uint32_t)(((2 * ks + b_gsel) ^ lr) << 4);
                LDSM_X4(b[nf2][0], b[nf2][1], b[nf2][2], b[nf2][3], addr);
            }
            uint32_t a[2][4];
#pragma unroll
            for (int mf = 0; mf < 2; mf++) {
                uint32_t addr = abase + aoff[mf] + (uint32_t)(((2 * ks + a_gsel) ^ lr) << 4);
                LDSM_X4(a[mf][0], a[mf][1], a[mf][2], a[mf][3], addr);
            }
#pragma unroll
            for (int mf = 0; mf < 2; mf++)
#pragma unroll
                for (int nf = 0; nf < 8; nf++) {
                    uint32_t b0 = b[nf >> 1][(nf & 1) * 2];
                    uint32_t b1 = b[nf >> 1][(nf & 1) * 2 + 1];
                    MMA_F16(acc[mf][nf], a[mf][0], a[mf][1], a[mf][2], a[mf][3], b0, b1);
                }
            if (do_lo) {
#pragma unroll
                for (int mf = 0; mf < 2; mf++) {
                    uint32_t addr = albase + aoff[mf] + (uint32_t)(((2 * ks + a_gsel) ^ lr) << 4);
                    LDSM_X4(a[mf][0], a[mf][1], a[mf][2], a[mf][3], addr);
                }
#pragma unroll
                for (int mf = 0; mf < 2; mf++)
#pragma unroll
                    for (int nf = 0; nf < 8; nf++) {
                        uint32_t b0 = b[nf >> 1][(nf & 1) * 2];
                        uint32_t b1 = b[nf >> 1][(nf & 1) * 2 + 1];
                        MMA_F16(acc[mf][nf], a[mf][0], a[mf][1], a[mf][2], a[mf][3], b0, b1);
                    }
            }
        }
    }

    int gid = lane >> 2, tig = lane & 3;
#pragma unroll
    for (int mf = 0; mf < 2; mf++) {
#pragma unroll
        for (int nf = 0; nf < 8; nf++) {
            int row0 = bm0 + wm * 32 + mf * 16 + gid;
            int col = bn0 + wn * 64 + nf * 8 + tig * 2;
            float bx = __ldg(&bias[col]);
            float by = __ldg(&bias[col + 1]);
            float v00 = fmaxf(acc[mf][nf][0] + bx, 0.f);
            float v01 = fmaxf(acc[mf][nf][1] + by, 0.f);
            float v10 = fmaxf(acc[mf][nf][2] + bx, 0.f);
            float v11 = fmaxf(acc[mf][nf][3] + by, 0.f);
            *reinterpret_cast<float2*>(&Cf[(size_t)row0 * DDIM + col]) = make_float2(v00, v01);
            *reinterpret_cast<float2*>(&Cf[(size_t)(row0 + 8) * DDIM + col]) = make_float2(v10, v11);
        }
    }
}

// ---------------------------------------------------------------------------
// Heads split-K GEMM
// ---------------------------------------------------------------------------
__global__ __launch_bounds__(256) void heads_partial(const float* __restrict__ w8c,
                                                     const float* __restrict__ w8d) {
    __shared__ float As[32][132];
    __shared__ float Bs[32][48];
    int r0 = blockIdx.x * 128;
    int ks = blockIdx.y;
    int k0 = ks * 512;
    int t = threadIdx.x;
    int ty = t >> 3, tx = t & 7;

    float acc[4][6];
#pragma unroll
    for (int i = 0; i < 4; i++)
#pragma unroll
        for (int j = 0; j < 6; j++) acc[i][j] = 0.f;

    for (int kc = 0; kc < 512; kc += 32) {
        for (int f = t; f < 1024; f += 256) {
            int r = f >> 3, q = f & 7;
            float4 v = *reinterpret_cast<const float4*>(&g_h2[(size_t)(r0 + r) * DDIM + k0 + kc + q * 4]);
            As[q * 4 + 0][r] = v.x; As[q * 4 + 1][r] = v.y;
            As[q * 4 + 2][r] = v.z; As[q * 4 + 3][r] = v.w;
        }
        for (int f = t; f < 336; f += 256) {
            int c = f >> 3, q = f & 7;
            const float* wr = (c < 21) ? (w8c + (size_t)c * DDIM) : (w8d + (size_t)(c - 21) * DDIM);
            float4 v = *reinterpret_cast<const float4*>(wr + k0 + kc + q * 4);
            Bs[q * 4 + 0][c] = v.x; Bs[q * 4 + 1][c] = v.y;
            Bs[q * 4 + 2][c] = v.z; Bs[q * 4 + 3][c] = v.w;
        }
        __syncthreads();
#pragma unroll
        for (int kk = 0; kk < 32; kk++) {
            float a[4], b[6];
#pragma unroll
            for (int i = 0; i < 4; i++) a[i] = As[kk][ty * 4 + i];
#pragma unroll
            for (int j = 0; j < 6; j++) b[j] = Bs[kk][tx * 6 + j];
#pragma unroll
            for (int i = 0; i < 4; i++)
#pragma unroll
                for (int j = 0; j < 6; j++) acc[i][j] = fmaf(a[i], b[j], acc[i][j]);
        }
        __syncthreads();
    }
#pragma unroll
    for (int i = 0; i < 4; i++) {
        int r = r0 + ty * 4 + i;
#pragma unroll
        for (int j = 0; j < 6; j++) {
            g_hpart[(size_t)ks * R_ROIS * 48 + (size_t)r * 48 + tx * 6 + j] = acc[i][j];
        }
    }
}

__global__ __launch_bounds__(256) void heads_reduce(const float* __restrict__ b8c,
                                                    const float* __restrict__ b8d) {
    int i = blockIdx.x * 256 + threadIdx.x;
    if (i >= R_ROIS * 42) return;
    int r = i / 42, c = i - r * 42;
    float s = 0.f;
#pragma unroll
    for (int ks = 0; ks < 8; ks++) s += g_hpart[(size_t)ks * R_ROIS * 48 + (size_t)r * 48 + c];
    if (c < 21) g_xc[r * NCLS + c] = fmaxf(s + b8c[c], 0.f);
    else        g_xd[r * NCLS + (c - 21)] = fmaxf(s + b8d[c - 21], 0.f);
}

// ---------------------------------------------------------------------------
// Softmax epilogue
// ---------------------------------------------------------------------------
__global__ __launch_bounds__(256) void colstats_kernel() {
    __shared__ float red[256];
    int c = blockIdx.x;
    int t = threadIdx.x;
    float m = -INFINITY;
    for (int r = t; r < R_ROIS; r += 256) m = fmaxf(m, g_xd[r * NCLS + c]);
    red[t] = m;
    __syncthreads();
    for (int s = 128; s; s >>= 1) {
        if (t < s) red[t] = fmaxf(red[t], red[t + s]);
        __syncthreads();
    }
    float cm = red[0];
    __syncthreads();
    float s2 = 0.f;
    for (int r = t; r < R_ROIS; r += 256) s2 += expf(g_xd[r * NCLS + c] - cm);
    red[t] = s2;
    __syncthreads();
    for (int s = 128; s; s >>= 1) {
        if (t < s) red[t] += red[t + s];
        __syncthreads();
    }
    if (t == 0) { g_colmax[c] = cm; g_colsum[c] = red[0]; }
}

__global__ __launch_bounds__(256) void finalize_kernel(float* __restrict__ out) {
    int warp = threadIdx.x >> 5;
    int lane = threadIdx.x & 31;
    int r = blockIdx.x * 8 + warp;
    if (r >= R_ROIS) return;

    float v = (lane < NCLS) ? g_xc[r * NCLS + lane] : -INFINITY;
    float m = v;
#pragma unroll
    for (int off = 16; off; off >>= 1) m = fmaxf(m, __shfl_xor_sync(0xFFFFFFFFu, m, off));
    float e = (lane < NCLS) ? expf(v - m) : 0.f;
    float s = e;
#pragma unroll
    for (int off = 16; off; off >>= 1) s += __shfl_xor_sync(0xFFFFFFFFu, s, off);

    if (lane < NCLS) {
        float dr = e / s;
        float smd = expf(g_xd[r * NCLS + lane] - g_colmax[lane]) / g_colsum[lane];
        out[OUT_DM + r * NCLS + lane] = dr * smd;
        out[OUT_DR + r * NCLS + lane] = dr;
    }
}

__global__ __launch_bounds__(256) void score_kernel(const float* __restrict__ dm,
                                                    float* __restrict__ score) {
    __shared__ float red[256];
    int c = blockIdx.x;
    int t = threadIdx.x;
    float s = 0.f;
    for (int r = t; r < R_ROIS; r += 256) s += dm[r * NCLS + c];
    red[t] = s;
    __syncthreads();
    for (int st = 128; st; st >>= 1) {
        if (t < st) red[t] += red[t + st];
        __syncthreads();
    }
    if (t == 0) score[c] = red[0];
}

// ---------------------------------------------------------------------------
// Launch — FC6 is launch #4 (profiler capture slot)
// ---------------------------------------------------------------------------
extern "C" void kernel_launch(void* const* d_in, const int* in_sizes, int n_in,
                              void* d_out, int out_size) {
    const float* x   = (const float*)d_in[0];
    const float* w6  = (const float*)d_in[1];
    const float* b6  = (const float*)d_in[2];
    const float* w7  = (const float*)d_in[3];
    const float* b7  = (const float*)d_in[4];
    const float* w8c = (const float*)d_in[5];
    const float* b8c = (const float*)d_in[6];
    const float* w8d = (const float*)d_in[7];
    const float* b8d = (const float*)d_in[8];
    const int*   ssw = (const int*)d_in[9];
    float* out = (float*)d_out;

    __half *p_yh, *p_yl, *p_w6h, *p_w7h, *p_h1h, *p_h1l;
    float *p_h2;
    cudaGetSymbolAddress((void**)&p_yh, g_yh);
    cudaGetSymbolAddress((void**)&p_yl, g_yl);
    cudaGetSymbolAddress((void**)&p_w6h, g_w6h);
    cudaGetSymbolAddress((void**)&p_w7h, g_w7h);
    cudaGetSymbolAddress((void**)&p_h1h, g_h1h);
    cudaGetSymbolAddress((void**)&p_h1l, g_h1l);
    cudaGetSymbolAddress((void**)&p_h2, g_h2);

    cudaFuncSetAttribute(gemm_mma64, cudaFuncAttributeMaxDynamicSharedMemorySize, SMEM64);
    cudaFuncSetAttribute(gemm_mma128, cudaFuncAttributeMaxDynamicSharedMemorySize, SMEM128);
    cudaFuncSetAttribute(pool_kernel, cudaFuncAttributeMaxDynamicSharedMemorySize, POOL_SMEM);

    // 1) FC6 weight prep
    wsum_h_kernel<<<(DDIM * KHALF / 4 + 255) / 256, 256>>>(w6);

    // 2) fused SPP pool (row-staged)
    {
        dim3 grid((NORI + PYP - 1) / PYP, CCH / PCH);
        pool_kernel<<<grid, 256, POOL_SMEM>>>(x);
    }

    // 3) SPP gather
    spp_gather_kernel<<<R_ROIS, 256>>>(ssw);

    // 4) FC6 (64x64, 3 CTA/SM), residual for quarter of K  [profiled]
    {
        dim3 grid(DDIM / 64, R_ROIS / 64);
        gemm_mma64<<<grid, 128, SMEM64>>>(p_yh, p_yl, p_w6h, b6, KHALF, 8, 1024,
                                          p_h1h, p_h1l);
    }

    // 5) FC7 weight prep
    w7_h_kernel<<<(DDIM * DDIM / 4 + 255) / 256, 256>>>(w7);

    // 6) FC7 (64x128, 2 CTA/SM), residual for quarter of K
    {
        dim3 grid(DDIM / 128, R_ROIS / 64);
        gemm_mma128<<<grid, 128, SMEM128>>>(p_h1h, p_h1l, p_w7h, b7, DDIM, 16, p_h2);
    }

    // 7) heads
    {
        dim3 grid(R_ROIS / 128, 8);
        heads_partial<<<grid, 256>>>(w8c, w8d);
        heads_reduce<<<(R_ROIS * 42 + 255) / 256, 256>>>(b8c, b8d);
    }

    // 8) softmax stats + finalize + score
    colstats_kernel<<<NCLS, 256>>>();
    finalize_kernel<<<R_ROIS / 8, 256>>>(out);
    score_kernel<<<NCLS, 256>>>(out + OUT_DM, out + OUT_SC);
}

// round 17
// speedup vs baseline: 1.3280x; 1.0592x over previous
#include <cuda_runtime.h>
#include <cuda_fp16.h>
#include <math.h>
#include <stdint.h>

// ---------------------------------------------------------------------------
// Problem constants
// ---------------------------------------------------------------------------
#define R_ROIS 2048
#define CCH    512
#define HWDIM  64
#define DDIM   4096
#define NCLS   21
#define KHALF  2048
#define NORI   58

#define OUT_DM 0
#define OUT_DR (R_ROIS * NCLS)
#define OUT_SC (2 * R_ROIS * NCLS)

// ---------------------------------------------------------------------------
// Scratch (device globals)
// ---------------------------------------------------------------------------
__device__ float g_vmax[NORI * NORI * CCH];
__device__ __half g_yh[R_ROIS * KHALF];
__device__ __half g_yl[R_ROIS * KHALF];
__device__ __half g_w6h[DDIM * KHALF];
__device__ __half g_w7h[DDIM * DDIM];
__device__ __half g_h1h[R_ROIS * DDIM];
__device__ __half g_h1l[R_ROIS * DDIM];
__device__ float g_h2[R_ROIS * DDIM];
__device__ float g_hpart[8 * R_ROIS * 48];
__device__ float g_xc[R_ROIS * NCLS];
__device__ float g_xd[R_ROIS * NCLS];
__device__ float g_colmax[NCLS];
__device__ float g_colsum[NCLS];

// ---------------------------------------------------------------------------
// Helpers
// ---------------------------------------------------------------------------
__device__ __forceinline__ uint32_t smem_u32(const void* p) {
    uint32_t a;
    asm("{ .reg .u64 t; cvta.to.shared.u64 t, %1; cvt.u32.u64 %0, t; }" : "=r"(a) : "l"(p));
    return a;
}

__device__ __forceinline__ void split2h(float v, __half& h, __half& l) {
    h = __float2half_rn(v);
    l = __float2half_rn(v - __half2float(h));
}

__device__ __forceinline__ uint32_t swz(int r, int g) {
    return (uint32_t)(r >> 3) * 1024u + (uint32_t)(r & 7) * 128u
         + (uint32_t)((g ^ (r & 7)) << 4);
}

#define CP_ASYNC16(dst, src) \
    asm volatile("cp.async.cg.shared.global [%0], [%1], 16;" :: "r"(dst), "l"(src))
#define CP_COMMIT() asm volatile("cp.async.commit_group;" ::: "memory")
#define CP_WAIT1()  asm volatile("cp.async.wait_group 1;" ::: "memory")

#define LDSM_X4(r0, r1, r2, r3, addr) \
    asm volatile("ldmatrix.sync.aligned.m8n8.x4.shared.b16 {%0,%1,%2,%3}, [%4];" \
                 : "=r"(r0), "=r"(r1), "=r"(r2), "=r"(r3) : "r"(addr))

#define MMA_F16(c, a0, a1, a2, a3, b0, b1) \
    asm volatile("mma.sync.aligned.m16n8k16.row.col.f32.f16.f16.f32 " \
                 "{%0,%1,%2,%3}, {%4,%5,%6,%7}, {%8,%9}, {%0,%1,%2,%3};" \
                 : "+f"((c)[0]), "+f"((c)[1]), "+f"((c)[2]), "+f"((c)[3]) \
                 : "r"(a0), "r"(a1), "r"(a2), "r"(a3), "r"(b0), "r"(b1))

// ---------------------------------------------------------------------------
// Fused SPP pool, row-staged
// ---------------------------------------------------------------------------
#define PCH 16
#define PYP 4
#define POOL_SMEM ((PCH * 10 * 64 + PCH * 10 * 61) * 4)

__global__ __launch_bounds__(256) void pool_kernel(const float* __restrict__ x) {
    extern __shared__ float psm[];
    float* raw = psm;                        // [PCH][10][64]
    float* hm  = psm + PCH * 10 * 64;        // [PCH][10][61]
    int yp0 = blockIdx.x * PYP;
    int cg = blockIdx.y;
    int t = threadIdx.x;
    int nyp = (yp0 + PYP <= NORI) ? PYP : (NORI - yp0);
    int nrow = nyp + 6;

    for (int idx = t; idx < PCH * nrow * 64; idx += 256) {
        int c = idx / (nrow * 64);
        int rem = idx - c * (nrow * 64);
        int row = rem >> 6;
        int xc = rem & 63;
        raw[(c * 10 + row) * 64 + xc] =
            x[((size_t)(cg * PCH + c) * HWDIM + (yp0 + row)) * HWDIM + xc];
    }
    __syncthreads();

    for (int idx = t; idx < PCH * nrow * NORI; idx += 256) {
        int c = idx / (nrow * NORI);
        int rem = idx - c * (nrow * NORI);
        int row = rem / NORI;
        int xp = rem - row * NORI;
        const float* rp = raw + (c * 10 + row) * 64 + xp;
        float m = rp[0];
#pragma unroll
        for (int d = 1; d < 7; d++) m = fmaxf(m, rp[d]);
        hm[(c * 10 + row) * 61 + xp] = m;
    }
    __syncthreads();

    for (int idx = t; idx < nyp * NORI * PCH; idx += 256) {
        int c = idx & (PCH - 1);
        int rest = idx >> 4;
        int xp = rest % NORI;
        int yl = rest / NORI;
        float m = hm[(c * 10 + yl) * 61 + xp];
#pragma unroll
        for (int y = 1; y < 7; y++) m = fmaxf(m, hm[(c * 10 + yl + y) * 61 + xp]);
        g_vmax[((size_t)(yp0 + yl) * NORI + xp) * CCH + cg * PCH + c] = m;
    }
}

// ---------------------------------------------------------------------------
// SPP gather: lv stored only for k < 256 (FC6 residual covers k < 256)
// ---------------------------------------------------------------------------
__global__ __launch_bounds__(256) void spp_gather_kernel(const int* __restrict__ ssw) {
    __shared__ float ys[KHALF];
    int r = blockIdx.x;
    int y0 = ssw[r * 4 + 0];
    int x0 = ssw[r * 4 + 1];
    int t = threadIdx.x;
#pragma unroll
    for (int q = 0; q < 4; q++) {
        int i = q >> 1, j = q & 1;
        const float* src = g_vmax + ((size_t)(y0 + 7 * i) * NORI + (x0 + 7 * j)) * CCH;
        for (int c0 = 0; c0 < CCH; c0 += 256) {
            int c = c0 + t;
            ys[c * 4 + q] = src[c];
        }
    }
    __syncthreads();
    int k0 = t * 8;
    __half hv[8], lv[8];
#pragma unroll
    for (int u = 0; u < 8; u++) split2h(ys[k0 + u], hv[u], lv[u]);
    *reinterpret_cast<uint4*>(&g_yh[(size_t)r * KHALF + k0]) = *reinterpret_cast<uint4*>(hv);
    if (k0 < 256)
        *reinterpret_cast<uint4*>(&g_yl[(size_t)r * KHALF + k0]) = *reinterpret_cast<uint4*>(lv);
}

// ---------------------------------------------------------------------------
// Weight fold + fp16 conversion
// ---------------------------------------------------------------------------
__global__ __launch_bounds__(256) void wsum_h_kernel(const float* __restrict__ w6) {
    int t = blockIdx.x * blockDim.x + threadIdx.x;
    const int NQ = DDIM * KHALF / 4;
    if (t >= NQ) return;
    int e = t / (KHALF / 4);
    int kq = t - e * (KHALF / 4);
    float4 av = reinterpret_cast<const float4*>(w6 + (size_t)e * DDIM)[kq];
    float4 bv = reinterpret_cast<const float4*>(w6 + (size_t)e * DDIM + KHALF)[kq];
    __half hv[4];
    hv[0] = __float2half_rn(av.x + bv.x);
    hv[1] = __float2half_rn(av.y + bv.y);
    hv[2] = __float2half_rn(av.z + bv.z);
    hv[3] = __float2half_rn(av.w + bv.w);
    *reinterpret_cast<uint2*>(&g_w6h[(size_t)e * KHALF + kq * 4]) = *reinterpret_cast<uint2*>(hv);
}

__global__ __launch_bounds__(256) void w7_h_kernel(const float* __restrict__ w7) {
    int t = blockIdx.x * blockDim.x + threadIdx.x;
    const int NQ = DDIM * DDIM / 4;
    if (t >= NQ) return;
    float4 v = reinterpret_cast<const float4*>(w7)[t];
    __half hv[4];
    hv[0] = __float2half_rn(v.x);
    hv[1] = __float2half_rn(v.y);
    hv[2] = __float2half_rn(v.z);
    hv[3] = __float2half_rn(v.w);
    *reinterpret_cast<uint2*>(&g_w7h[(size_t)t * 4]) = *reinterpret_cast<uint2*>(hv);
}

// ---------------------------------------------------------------------------
// GEMM variant A (FC6): CTA 64x64, 3 CTAs/SM, stage 24KB x3.
// Residual (Al) pass only for chunks kb < lo_nch; Cl stored when bn0 < cl_cols.
// ---------------------------------------------------------------------------
#define STG64 24576
#define SMEM64 (3 * STG64)

__device__ __forceinline__ void load_stage64(
    const __half* __restrict__ Ah, const __half* __restrict__ Al,
    const __half* __restrict__ Bh,
    int Kb, int bm0, int bn0, int k0, uint32_t sbase, int tid, bool load_al) {
#pragma unroll
    for (int it = 0; it < 12; it++) {
        int f = tid + it * 128;
        const __half* src;
        uint32_t dst;
        if (f < 512) {
            int r = f >> 3, g = f & 7;
            src = Ah + (size_t)(bm0 + r) * Kb + k0 + g * 8;
            dst = sbase + swz(r, g);
        } else if (f < 1024) {
            if (!load_al) continue;
            int fl = f - 512;
            int r = fl >> 3, g = fl & 7;
            src = Al + (size_t)(bm0 + r) * Kb + k0 + g * 8;
            dst = sbase + 8192u + swz(r, g);
        } else {
            int fl = f - 1024;
            int r = fl >> 3, g = fl & 7;
            src = Bh + (size_t)(bn0 + r) * Kb + k0 + g * 8;
            dst = sbase + 16384u + swz(r, g);
        }
        CP_ASYNC16(dst, src);
    }
}

__global__ __launch_bounds__(128, 3) void gemm_mma64(
    const __half* __restrict__ Ah, const __half* __restrict__ Al,
    const __half* __restrict__ Bh,
    const float* __restrict__ bias, int Kb, int lo_nch, int cl_cols,
    __half* __restrict__ Ch, __half* __restrict__ Cl) {
    extern __shared__ __align__(128) char smp[];
    uint32_t s0 = smem_u32(smp);

    int tid = threadIdx.x;
    int wid = tid >> 5;
    int lane = tid & 31;
    int wm = wid & 1;
    int wn = wid >> 1;
    int bm0 = blockIdx.y * 64;
    int bn0 = blockIdx.x * 64;

    int lr = lane & 7;
    int a_add8 = (lane >> 3) & 1;
    int a_gsel = lane >> 4;
    int b_add8 = lane >> 4;
    int b_gsel = (lane >> 3) & 1;

    uint32_t aoff[2], boff[2];
#pragma unroll
    for (int mf = 0; mf < 2; mf++)
        aoff[mf] = (uint32_t)(wm * 4 + mf * 2 + a_add8) * 1024u + (uint32_t)lr * 128u;
#pragma unroll
    for (int nf2 = 0; nf2 < 2; nf2++)
        boff[nf2] = (uint32_t)(wn * 4 + nf2 * 2 + b_add8) * 1024u + (uint32_t)lr * 128u;

    float acc[2][4][4];
#pragma unroll
    for (int i = 0; i < 2; i++)
#pragma unroll
        for (int j = 0; j < 4; j++)
#pragma unroll
            for (int q = 0; q < 4; q++) acc[i][j][q] = 0.f;

    int nch = Kb >> 6;

    load_stage64(Ah, Al, Bh, Kb, bm0, bn0, 0, s0, tid, 0 < lo_nch);
    CP_COMMIT();
    load_stage64(Ah, Al, Bh, Kb, bm0, bn0, 64, s0 + STG64, tid, 1 < lo_nch);
    CP_COMMIT();

    for (int kb = 0; kb < nch; kb++) {
        CP_WAIT1();
        __syncthreads();

        int nk = kb + 2;
        if (nk < nch) {
            load_stage64(Ah, Al, Bh, Kb, bm0, bn0, nk * 64,
                         s0 + (uint32_t)(nk % 3) * STG64, tid, nk < lo_nch);
        }
        CP_COMMIT();

        uint32_t abase = s0 + (uint32_t)(kb % 3) * STG64;
        uint32_t albase = abase + 8192u;
        uint32_t bbase = abase + 16384u;
        bool do_lo = (kb < lo_nch);

#pragma unroll
        for (int ks = 0; ks < 4; ks++) {
            uint32_t b[2][4];
#pragma unroll
            for (int nf2 = 0; nf2 < 2; nf2++) {
                uint32_t addr = bbase + boff[nf2] + (uint32_t)(((2 * ks + b_gsel) ^ lr) << 4);
                LDSM_X4(b[nf2][0], b[nf2][1], b[nf2][2], b[nf2][3], addr);
            }
            uint32_t a[2][4];
#pragma unroll
            for (int mf = 0; mf < 2; mf++) {
                uint32_t addr = abase + aoff[mf] + (uint32_t)(((2 * ks + a_gsel) ^ lr) << 4);
                LDSM_X4(a[mf][0], a[mf][1], a[mf][2], a[mf][3], addr);
            }
#pragma unroll
            for (int mf = 0; mf < 2; mf++)
#pragma unroll
                for (int nf = 0; nf < 4; nf++) {
                    uint32_t b0 = b[nf >> 1][(nf & 1) * 2];
                    uint32_t b1 = b[nf >> 1][(nf & 1) * 2 + 1];
                    MMA_F16(acc[mf][nf], a[mf][0], a[mf][1], a[mf][2], a[mf][3], b0, b1);
                }
            if (do_lo) {
#pragma unroll
                for (int mf = 0; mf < 2; mf++) {
                    uint32_t addr = albase + aoff[mf] + (uint32_t)(((2 * ks + a_gsel) ^ lr) << 4);
                    LDSM_X4(a[mf][0], a[mf][1], a[mf][2], a[mf][3], addr);
                }
#pragma unroll
                for (int mf = 0; mf < 2; mf++)
#pragma unroll
                    for (int nf = 0; nf < 4; nf++) {
                        uint32_t b0 = b[nf >> 1][(nf & 1) * 2];
                        uint32_t b1 = b[nf >> 1][(nf & 1) * 2 + 1];
                        MMA_F16(acc[mf][nf], a[mf][0], a[mf][1], a[mf][2], a[mf][3], b0, b1);
                    }
            }
        }
    }

    bool write_l = (bn0 < cl_cols);
    int gid = lane >> 2, tig = lane & 3;
#pragma unroll
    for (int mf = 0; mf < 2; mf++) {
#pragma unroll
        for (int nf = 0; nf < 4; nf++) {
            int row0 = bm0 + wm * 32 + mf * 16 + gid;
            int col = bn0 + wn * 32 + nf * 8 + tig * 2;
            float bx = __ldg(&bias[col]);
            float by = __ldg(&bias[col + 1]);
            float v00 = fmaxf(acc[mf][nf][0] + bx, 0.f);
            float v01 = fmaxf(acc[mf][nf][1] + by, 0.f);
            float v10 = fmaxf(acc[mf][nf][2] + bx, 0.f);
            float v11 = fmaxf(acc[mf][nf][3] + by, 0.f);
            __half h0, l0, h1, l1;
            split2h(v00, h0, l0); split2h(v01, h1, l1);
            *reinterpret_cast<__half2*>(&Ch[(size_t)row0 * DDIM + col]) = __halves2half2(h0, h1);
            if (write_l)
                *reinterpret_cast<__half2*>(&Cl[(size_t)row0 * DDIM + col]) = __halves2half2(l0, l1);
            split2h(v10, h0, l0); split2h(v11, h1, l1);
            *reinterpret_cast<__half2*>(&Ch[(size_t)(row0 + 8) * DDIM + col]) = __halves2half2(h0, h1);
            if (write_l)
                *reinterpret_cast<__half2*>(&Cl[(size_t)(row0 + 8) * DDIM + col]) = __halves2half2(l0, l1);
        }
    }
}

// ---------------------------------------------------------------------------
// GEMM variant B (FC7): CTA 64x128, 2 CTAs/SM, stage 32KB x3.
// Residual (Al) pass only for chunks kb < lo_nch.
// ---------------------------------------------------------------------------
#define STG128 32768
#define SMEM128 (3 * STG128)

__device__ __forceinline__ void load_stage128(
    const __half* __restrict__ Ah, const __half* __restrict__ Al,
    const __half* __restrict__ Bh,
    int Kb, int bm0, int bn0, int k0, uint32_t sbase, int tid, bool load_al) {
#pragma unroll
    for (int it = 0; it < 16; it++) {
        int f = tid + it * 128;
        const __half* src;
        uint32_t dst;
        if (f < 512) {
            int r = f >> 3, g = f & 7;
            src = Ah + (size_t)(bm0 + r) * Kb + k0 + g * 8;
            dst = sbase + swz(r, g);
        } else if (f < 1024) {
            if (!load_al) continue;
            int fl = f - 512;
            int r = fl >> 3, g = fl & 7;
            src = Al + (size_t)(bm0 + r) * Kb + k0 + g * 8;
            dst = sbase + 8192u + swz(r, g);
        } else {
            int fl = f - 1024;
            int r = fl >> 3, g = fl & 7;
            src = Bh + (size_t)(bn0 + r) * Kb + k0 + g * 8;
            dst = sbase + 16384u + swz(r, g);
        }
        CP_ASYNC16(dst, src);
    }
}

__global__ __launch_bounds__(128, 2) void gemm_mma128(
    const __half* __restrict__ Ah, const __half* __restrict__ Al,
    const __half* __restrict__ Bh,
    const float* __restrict__ bias, int Kb, int lo_nch,
    float* __restrict__ Cf) {
    extern __shared__ __align__(128) char smp[];
    uint32_t s0 = smem_u32(smp);

    int tid = threadIdx.x;
    int wid = tid >> 5;
    int lane = tid & 31;
    int wm = wid & 1;
    int wn = wid >> 1;
    int bm0 = blockIdx.y * 64;
    int bn0 = blockIdx.x * 128;

    int lr = lane & 7;
    int a_add8 = (lane >> 3) & 1;
    int a_gsel = lane >> 4;
    int b_add8 = lane >> 4;
    int b_gsel = (lane >> 3) & 1;

    uint32_t aoff[2], boff[4];
#pragma unroll
    for (int mf = 0; mf < 2; mf++)
        aoff[mf] = (uint32_t)(wm * 4 + mf * 2 + a_add8) * 1024u + (uint32_t)lr * 128u;
#pragma unroll
    for (int nf2 = 0; nf2 < 4; nf2++)
        boff[nf2] = (uint32_t)(wn * 8 + nf2 * 2 + b_add8) * 1024u + (uint32_t)lr * 128u;

    float acc[2][8][4];
#pragma unroll
    for (int i = 0; i < 2; i++)
#pragma unroll
        for (int j = 0; j < 8; j++)
#pragma unroll
            for (int q = 0; q < 4; q++) acc[i][j][q] = 0.f;

    int nch = Kb >> 6;

    load_stage128(Ah, Al, Bh, Kb, bm0, bn0, 0, s0, tid, 0 < lo_nch);
    CP_COMMIT();
    load_stage128(Ah, Al, Bh, Kb, bm0, bn0, 64, s0 + STG128, tid, 1 < lo_nch);
    CP_COMMIT();

    for (int kb = 0; kb < nch; kb++) {
        CP_WAIT1();
        __syncthreads();

        int nk = kb + 2;
        if (nk < nch) {
            load_stage128(Ah, Al, Bh, Kb, bm0, bn0, nk * 64,
                          s0 + (uint32_t)(nk % 3) * STG128, tid, nk < lo_nch);
        }
        CP_COMMIT();

        uint32_t abase = s0 + (uint32_t)(kb % 3) * STG128;
        uint32_t albase = abase + 8192u;
        uint32_t bbase = abase + 16384u;
        bool do_lo = (kb < lo_nch);

#pragma unroll
        for (int ks = 0; ks < 4; ks++) {
            uint32_t b[4][4];
#pragma unroll
            for (int nf2 = 0; nf2 < 4; nf2++) {
                uint32_t addr = bbase + boff[nf2] + (uint32_t)(((2 * ks + b_gsel) ^ lr) << 4);
                LDSM_X4(b[nf2][0], b[nf2][1], b[nf2][2], b[nf2][3], addr);
            }
            uint32_t a[2][4];
#pragma unroll
            for (int mf = 0; mf < 2; mf++) {
                uint32_t addr = abase + aoff[mf] + (uint32_t)(((2 * ks + a_gsel) ^ lr) << 4);
                LDSM_X4(a[mf][0], a[mf][1], a[mf][2], a[mf][3], addr);
            }
#pragma unroll
            for (int mf = 0; mf < 2; mf++)
#pragma unroll
                for (int nf = 0; nf < 8; nf++) {
                    uint32_t b0 = b[nf >> 1][(nf & 1) * 2];
                    uint32_t b1 = b[nf >> 1][(nf & 1) * 2 + 1];
                    MMA_F16(acc[mf][nf], a[mf][0], a[mf][1], a[mf][2], a[mf][3], b0, b1);
                }
            if (do_lo) {
#pragma unroll
                for (int mf = 0; mf < 2; mf++) {
                    uint32_t addr = albase + aoff[mf] + (uint32_t)(((2 * ks + a_gsel) ^ lr) << 4);
                    LDSM_X4(a[mf][0], a[mf][1], a[mf][2], a[mf][3], addr);
                }
#pragma unroll
                for (int mf = 0; mf < 2; mf++)
#pragma unroll
                    for (int nf = 0; nf < 8; nf++) {
                        uint32_t b0 = b[nf >> 1][(nf & 1) * 2];
                        uint32_t b1 = b[nf >> 1][(nf & 1) * 2 + 1];
                        MMA_F16(acc[mf][nf], a[mf][0], a[mf][1], a[mf][2], a[mf][3], b0, b1);
                    }
            }
        }
    }

    int gid = lane >> 2, tig = lane & 3;
#pragma unroll
    for (int mf = 0; mf < 2; mf++) {
#pragma unroll
        for (int nf = 0; nf < 8; nf++) {
            int row0 = bm0 + wm * 32 + mf * 16 + gid;
            int col = bn0 + wn * 64 + nf * 8 + tig * 2;
            float bx = __ldg(&bias[col]);
            float by = __ldg(&bias[col + 1]);
            float v00 = fmaxf(acc[mf][nf][0] + bx, 0.f);
            float v01 = fmaxf(acc[mf][nf][1] + by, 0.f);
            float v10 = fmaxf(acc[mf][nf][2] + bx, 0.f);
            float v11 = fmaxf(acc[mf][nf][3] + by, 0.f);
            *reinterpret_cast<float2*>(&Cf[(size_t)row0 * DDIM + col]) = make_float2(v00, v01);
            *reinterpret_cast<float2*>(&Cf[(size_t)(row0 + 8) * DDIM + col]) = make_float2(v10, v11);
        }
    }
}

// ---------------------------------------------------------------------------
// Heads split-K GEMM
// ---------------------------------------------------------------------------
__global__ __launch_bounds__(256) void heads_partial(const float* __restrict__ w8c,
                                                     const float* __restrict__ w8d) {
    __shared__ float As[32][132];
    __shared__ float Bs[32][48];
    int r0 = blockIdx.x * 128;
    int ks = blockIdx.y;
    int k0 = ks * 512;
    int t = threadIdx.x;
    int ty = t >> 3, tx = t & 7;

    float acc[4][6];
#pragma unroll
    for (int i = 0; i < 4; i++)
#pragma unroll
        for (int j = 0; j < 6; j++) acc[i][j] = 0.f;

    for (int kc = 0; kc < 512; kc += 32) {
        for (int f = t; f < 1024; f += 256) {
            int r = f >> 3, q = f & 7;
            float4 v = *reinterpret_cast<const float4*>(&g_h2[(size_t)(r0 + r) * DDIM + k0 + kc + q * 4]);
            As[q * 4 + 0][r] = v.x; As[q * 4 + 1][r] = v.y;
            As[q * 4 + 2][r] = v.z; As[q * 4 + 3][r] = v.w;
        }
        for (int f = t; f < 336; f += 256) {
            int c = f >> 3, q = f & 7;
            const float* wr = (c < 21) ? (w8c + (size_t)c * DDIM) : (w8d + (size_t)(c - 21) * DDIM);
            float4 v = *reinterpret_cast<const float4*>(wr + k0 + kc + q * 4);
            Bs[q * 4 + 0][c] = v.x; Bs[q * 4 + 1][c] = v.y;
            Bs[q * 4 + 2][c] = v.z; Bs[q * 4 + 3][c] = v.w;
        }
        __syncthreads();
#pragma unroll
        for (int kk = 0; kk < 32; kk++) {
            float a[4], b[6];
#pragma unroll
            for (int i = 0; i < 4; i++) a[i] = As[kk][ty * 4 + i];
#pragma unroll
            for (int j = 0; j < 6; j++) b[j] = Bs[kk][tx * 6 + j];
#pragma unroll
            for (int i = 0; i < 4; i++)
#pragma unroll
                for (int j = 0; j < 6; j++) acc[i][j] = fmaf(a[i], b[j], acc[i][j]);
        }
        __syncthreads();
    }
#pragma unroll
    for (int i = 0; i < 4; i++) {
        int r = r0 + ty * 4 + i;
#pragma unroll
        for (int j = 0; j < 6; j++) {
            g_hpart[(size_t)ks * R_ROIS * 48 + (size_t)r * 48 + tx * 6 + j] = acc[i][j];
        }
    }
}

__global__ __launch_bounds__(256) void heads_reduce(const float* __restrict__ b8c,
                                                    const float* __restrict__ b8d) {
    int i = blockIdx.x * 256 + threadIdx.x;
    if (i >= R_ROIS * 42) return;
    int r = i / 42, c = i - r * 42;
    float s = 0.f;
#pragma unroll
    for (int ks = 0; ks < 8; ks++) s += g_hpart[(size_t)ks * R_ROIS * 48 + (size_t)r * 48 + c];
    if (c < 21) g_xc[r * NCLS + c] = fmaxf(s + b8c[c], 0.f);
    else        g_xd[r * NCLS + (c - 21)] = fmaxf(s + b8d[c - 21], 0.f);
}

// ---------------------------------------------------------------------------
// Softmax epilogue
// ---------------------------------------------------------------------------
__global__ __launch_bounds__(256) void colstats_kernel() {
    __shared__ float red[256];
    int c = blockIdx.x;
    int t = threadIdx.x;
    float m = -INFINITY;
    for (int r = t; r < R_ROIS; r += 256) m = fmaxf(m, g_xd[r * NCLS + c]);
    red[t] = m;
    __syncthreads();
    for (int s = 128; s; s >>= 1) {
        if (t < s) red[t] = fmaxf(red[t], red[t + s]);
        __syncthreads();
    }
    float cm = red[0];
    __syncthreads();
    float s2 = 0.f;
    for (int r = t; r < R_ROIS; r += 256) s2 += expf(g_xd[r * NCLS + c] - cm);
    red[t] = s2;
    __syncthreads();
    for (int s = 128; s; s >>= 1) {
        if (t < s) red[t] += red[t + s];
        __syncthreads();
    }
    if (t == 0) { g_colmax[c] = cm; g_colsum[c] = red[0]; }
}

__global__ __launch_bounds__(256) void finalize_kernel(float* __restrict__ out) {
    int warp = threadIdx.x >> 5;
    int lane = threadIdx.x & 31;
    int r = blockIdx.x * 8 + warp;
    if (r >= R_ROIS) return;

    float v = (lane < NCLS) ? g_xc[r * NCLS + lane] : -INFINITY;
    float m = v;
#pragma unroll
    for (int off = 16; off; off >>= 1) m = fmaxf(m, __shfl_xor_sync(0xFFFFFFFFu, m, off));
    float e = (lane < NCLS) ? expf(v - m) : 0.f;
    float s = e;
#pragma unroll
    for (int off = 16; off; off >>= 1) s += __shfl_xor_sync(0xFFFFFFFFu, s, off);

    if (lane < NCLS) {
        float dr = e / s;
        float smd = expf(g_xd[r * NCLS + lane] - g_colmax[lane]) / g_colsum[lane];
        out[OUT_DM + r * NCLS + lane] = dr * smd;
        out[OUT_DR + r * NCLS + lane] = dr;
    }
}

__global__ __launch_bounds__(256) void score_kernel(const float* __restrict__ dm,
                                                    float* __restrict__ score) {
    __shared__ float red[256];
    int c = blockIdx.x;
    int t = threadIdx.x;
    float s = 0.f;
    for (int r = t; r < R_ROIS; r += 256) s += dm[r * NCLS + c];
    red[t] = s;
    __syncthreads();
    for (int st = 128; st; st >>= 1) {
        if (t < st) red[t] += red[t + st];
        __syncthreads();
    }
    if (t == 0) score[c] = red[0];
}

// ---------------------------------------------------------------------------
// Launch — FC6 is launch #4 (profiler capture slot)
// ---------------------------------------------------------------------------
extern "C" void kernel_launch(void* const* d_in, const int* in_sizes, int n_in,
                              void* d_out, int out_size) {
    const float* x   = (const float*)d_in[0];
    const float* w6  = (const float*)d_in[1];
    const float* b6  = (const float*)d_in[2];
    const float* w7  = (const float*)d_in[3];
    const float* b7  = (const float*)d_in[4];
    const float* w8c = (const float*)d_in[5];
    const float* b8c = (const float*)d_in[6];
    const float* w8d = (const float*)d_in[7];
    const float* b8d = (const float*)d_in[8];
    const int*   ssw = (const int*)d_in[9];
    float* out = (float*)d_out;

    __half *p_yh, *p_yl, *p_w6h, *p_w7h, *p_h1h, *p_h1l;
    float *p_h2;
    cudaGetSymbolAddress((void**)&p_yh, g_yh);
    cudaGetSymbolAddress((void**)&p_yl, g_yl);
    cudaGetSymbolAddress((void**)&p_w6h, g_w6h);
    cudaGetSymbolAddress((void**)&p_w7h, g_w7h);
    cudaGetSymbolAddress((void**)&p_h1h, g_h1h);
    cudaGetSymbolAddress((void**)&p_h1l, g_h1l);
    cudaGetSymbolAddress((void**)&p_h2, g_h2);

    cudaFuncSetAttribute(gemm_mma64, cudaFuncAttributeMaxDynamicSharedMemorySize, SMEM64);
    cudaFuncSetAttribute(gemm_mma128, cudaFuncAttributeMaxDynamicSharedMemorySize, SMEM128);
    cudaFuncSetAttribute(pool_kernel, cudaFuncAttributeMaxDynamicSharedMemorySize, POOL_SMEM);

    // 1) FC6 weight prep
    wsum_h_kernel<<<(DDIM * KHALF / 4 + 255) / 256, 256>>>(w6);

    // 2) fused SPP pool (row-staged)
    {
        dim3 grid((NORI + PYP - 1) / PYP, CCH / PCH);
        pool_kernel<<<grid, 256, POOL_SMEM>>>(x);
    }

    // 3) SPP gather
    spp_gather_kernel<<<R_ROIS, 256>>>(ssw);

    // 4) FC6 (64x64, 3 CTA/SM), residual for eighth of K  [profiled]
    {
        dim3 grid(DDIM / 64, R_ROIS / 64);
        gemm_mma64<<<grid, 128, SMEM64>>>(p_yh, p_yl, p_w6h, b6, KHALF, 4, 512,
                                          p_h1h, p_h1l);
    }

    // 5) FC7 weight prep
    w7_h_kernel<<<(DDIM * DDIM / 4 + 255) / 256, 256>>>(w7);

    // 6) FC7 (64x128, 2 CTA/SM), residual for eighth of K
    {
        dim3 grid(DDIM / 128, R_ROIS / 64);
        gemm_mma128<<<grid, 128, SMEM128>>>(p_h1h, p_h1l, p_w7h, b7, DDIM, 8, p_h2);
    }

    // 7) heads
    {
        dim3 grid(R_ROIS / 128, 8);
        heads_partial<<<grid, 256>>>(w8c, w8d);
        heads_reduce<<<(R_ROIS * 42 + 255) / 256, 256>>>(b8c, b8d);
    }

    // 8) softmax stats + finalize + score
    colstats_kernel<<<NCLS, 256>>>();
    finalize_kernel<<<R_ROIS / 8, 256>>>(out);
    score_kernel<<<NCLS, 256>>>(out + OUT_DM, out + OUT_SC);
}